// round 11
// baseline (speedup 1.0000x reference)
#include <cuda_runtime.h>
#include <cuda_fp16.h>
#include <math_constants.h>
#include <cstdint>

// Problem constants
#define BQ   4
#define LQ   4096
#define DQ   128
#define NBQ  64
#define MTOT (BQ * LQ)     // 16384 rows

// ---------------------------------------------------------------------------
// Scratch (__device__ globals; no allocations allowed)
// A-side operands fp16 hi/lo (exact to ~2^-22); B-side single fp16.
// ---------------------------------------------------------------------------
__device__ __half g_Wq[768 * 768];           // W_qkv, single fp16 (B operand)
__device__ __half g_QKVh[6 * MTOT * DQ];     // Q planes: hi; K/V planes: single
__device__ __half g_QKVl[6 * MTOT * DQ];     // Q planes: lo (K/V region unused)
__device__ __half g_Ath[MTOT * 256];         // attention out hi/lo (A operand)
__device__ __half g_Atl[MTOT * 256];
__device__ __half g_Wo[256 * 256];           // W_out, single fp16
__device__ int g_cnt[NBQ];
__device__ int g_list[NBQ][NBQ];

// ---------------------------------------------------------------------------
// Helpers
// ---------------------------------------------------------------------------
__device__ __forceinline__ uint32_t smem_to_u32(const void* p) {
    uint32_t a;
    asm("{ .reg .u64 t; cvta.to.shared.u64 t, %1; cvt.u32.u64 %0, t; }" : "=r"(a) : "l"(p));
    return a;
}
__device__ __forceinline__ void cp16(uint32_t dst_smem, const void* src) {
    asm volatile("cp.async.cg.shared.global [%0], [%1], 16;" :: "r"(dst_smem), "l"(src));
}
#define CP_COMMIT() asm volatile("cp.async.commit_group;" ::: "memory")
#define CP_WAIT(n)  asm volatile("cp.async.wait_group %0;" :: "n"(n) : "memory")

__device__ __forceinline__ void ldmx4(uint32_t* r, uint32_t addr) {
    asm volatile("ldmatrix.sync.aligned.m8n8.x4.shared.b16 {%0,%1,%2,%3}, [%4];"
                 : "=r"(r[0]), "=r"(r[1]), "=r"(r[2]), "=r"(r[3]) : "r"(addr));
}
__device__ __forceinline__ void ldmx4t(uint32_t* r, uint32_t addr) {
    asm volatile("ldmatrix.sync.aligned.m8n8.x4.trans.shared.b16 {%0,%1,%2,%3}, [%4];"
                 : "=r"(r[0]), "=r"(r[1]), "=r"(r[2]), "=r"(r[3]) : "r"(addr));
}
__device__ __forceinline__ void ldmx2(uint32_t* r, uint32_t addr) {
    asm volatile("ldmatrix.sync.aligned.m8n8.x2.shared.b16 {%0,%1}, [%2];"
                 : "=r"(r[0]), "=r"(r[1]) : "r"(addr));
}
__device__ __forceinline__ void mma_fp16(float* c, const uint32_t* a,
                                         uint32_t b0, uint32_t b1) {
    asm volatile(
        "mma.sync.aligned.m16n8k16.row.col.f32.f16.f16.f32 "
        "{%0,%1,%2,%3}, {%4,%5,%6,%7}, {%8,%9}, {%0,%1,%2,%3};"
        : "+f"(c[0]), "+f"(c[1]), "+f"(c[2]), "+f"(c[3])
        : "r"(a[0]), "r"(a[1]), "r"(a[2]), "r"(a[3]), "r"(b0), "r"(b1));
}
__device__ __forceinline__ uint32_t pack_h2(float a, float b) {
    __half2 t = __floats2half2_rn(a, b);
    return *(uint32_t*)&t;
}
__device__ __forceinline__ void split2h(float a, float b, uint32_t& h, uint32_t& l) {
    __half ha = __float2half_rn(a);
    __half hb = __float2half_rn(b);
    h = ((uint32_t)__half_as_ushort(hb) << 16) | __half_as_ushort(ha);
    l = pack_h2(a - __half2float(ha), b - __half2float(hb));
}

// ---------------------------------------------------------------------------
// Block-mask compaction (per-qblock lists)
// ---------------------------------------------------------------------------
__global__ void build_mask_kernel(const void* __restrict__ mask)
{
    int qb = threadIdx.x;
    if (qb >= NBQ) return;
    const float* mf = (const float*)mask;
    const int*   mi = (const int*)mask;
    const unsigned char* mb = (const unsigned char*)mask;
    int mode;
    if (mf[0] == 1.0f)   mode = 0;
    else if (mi[0] == 1) mode = 1;
    else                 mode = 2;
    int cnt = 0;
    for (int kb = 0; kb <= qb; kb++) {
        size_t idx = (size_t)(qb * 64) * (size_t)LQ + (size_t)(kb * 64);
        bool on;
        if (mode == 0)      on = (mf[idx] != 0.0f);
        else if (mode == 1) on = (mi[idx] != 0);
        else                on = (mb[idx] != 0);
        if (on) g_list[qb][cnt++] = kb;
    }
    g_cnt[qb] = cnt;
}

// fp32 -> single fp16 (weights, B operand)
__global__ void cvt_kernel(const float4* __restrict__ src,
                           uint2* __restrict__ dst, int n4)
{
    int i = blockIdx.x * 256 + threadIdx.x;
    if (i >= n4) return;
    float4 v = src[i];
    dst[i] = make_uint2(pack_h2(v.x, v.y), pack_h2(v.z, v.w));
}

// ---------------------------------------------------------------------------
// Shared GEMM geometry: tile 128(M) x 128(N) x 32(K), 8 warps (2M x 4N),
// warp tile 64x32 (acc[4][4][4] = 64 regs) -> 2 CTAs/SM (16 warps/SM).
// smem rows stride 40 fp16 (80B, conflict-free ldmatrix).
// ---------------------------------------------------------------------------
#define GSTRIDE 40
#define A_MATB  (128 * GSTRIDE * 2)     // 10240 B per matrix tile
#define STAGEB  (3 * A_MATB)            // Ah, Al, B = 30720
#define GEMM_SMEM (2 * STAGEB)          // 61440 (x2 CTAs = 122880 <= 227KB)

// ---------------------------------------------------------------------------
// QKV GEMM: Y[16384,768] = X @ Wq^T + b. A = X fp32 (6 planes), converted to
// fp16 hi/lo IN THE LOADER (register-pipelined). 2-term: D = Ah@B + Al@B.
// Grid (6, 128): blockIdx.x = output plane. Planes 0,1 (Q) -> hi/lo out;
// planes 2..5 (K,V) -> single fp16 out.
// ---------------------------------------------------------------------------
__global__ __launch_bounds__(256, 2) void gemm_qkv(
    const float* __restrict__ x0, const float* __restrict__ x1,
    const float* __restrict__ x2, const float* __restrict__ x3,
    const float* __restrict__ x4, const float* __restrict__ x5,
    const __half* __restrict__ W, const float* __restrict__ bias)
{
    constexpr int NCH = 24;   // 768 / 32

    extern __shared__ __align__(128) char smc[];
    uint32_t sbase0 = smem_to_u32(smc);

    int tid  = threadIdx.x;
    int warp = tid >> 5, lane = tid & 31;
    int wm = warp & 1;
    int wn = warp >> 1;
    int m0 = blockIdx.y * 128;
    int n0 = blockIdx.x * 128;

    float4 pre[4];   // A prefetch: 2 chunks x 8 fp32 per thread

    auto ldA = [&](int ch) {
        int k0 = ch * 32;
        int pl = k0 >> 7, kc = k0 & 127;
        const float* xp = (pl == 0) ? x0 : (pl == 1) ? x1 : (pl == 2) ? x2
                        : (pl == 3) ? x3 : (pl == 4) ? x4 : x5;
#pragma unroll
        for (int i = 0; i < 2; i++) {
            int e = tid + i * 256;
            int r = e >> 2, seg = e & 3;
            const float* s = xp + (size_t)(m0 + r) * 128 + kc + seg * 8;
            pre[2 * i]     = *(const float4*)s;
            pre[2 * i + 1] = *(const float4*)(s + 4);
        }
    };
    auto stsA = [&](int buf) {
        char* base = smc + buf * STAGEB;
#pragma unroll
        for (int i = 0; i < 2; i++) {
            int e = tid + i * 256;
            int r = e >> 2, seg = e & 3;
            float4 v0 = pre[2 * i], v1 = pre[2 * i + 1];
            uint32_t h[4], l[4];
            split2h(v0.x, v0.y, h[0], l[0]);
            split2h(v0.z, v0.w, h[1], l[1]);
            split2h(v1.x, v1.y, h[2], l[2]);
            split2h(v1.z, v1.w, h[3], l[3]);
            uint32_t off = (uint32_t)(r * GSTRIDE + seg * 8) * 2;
            *(uint4*)(base + off)          = make_uint4(h[0], h[1], h[2], h[3]);
            *(uint4*)(base + A_MATB + off) = make_uint4(l[0], l[1], l[2], l[3]);
        }
    };
    auto ldB = [&](int ch, int buf) {
        int k0 = ch * 32;
        uint32_t sbB = sbase0 + buf * STAGEB + 2 * A_MATB;
#pragma unroll
        for (int i = 0; i < 2; i++) {
            int e = tid + i * 256;           // 128 rows x 4 chunks
            int r = e >> 2, seg = e & 3;
            size_t gb = (size_t)(n0 + r) * 768 + k0 + seg * 8;
            cp16(sbB + (uint32_t)(r * GSTRIDE + seg * 8) * 2, W + gb);
        }
    };

    float acc[4][4][4];
#pragma unroll
    for (int mf = 0; mf < 4; mf++)
#pragma unroll
        for (int nf = 0; nf < 4; nf++)
#pragma unroll
            for (int j = 0; j < 4; j++) acc[mf][nf][j] = 0.f;

    ldA(0); stsA(0); ldB(0, 0); CP_COMMIT();
    ldA(1); stsA(1); ldB(1, 1); CP_COMMIT();
    CP_WAIT(1);
    __syncthreads();

    int li = lane & 15;
    uint32_t a_row_off = (uint32_t)((wm * 64 + li) * GSTRIDE) * 2;
    uint32_t a_col_off = (uint32_t)((lane >> 4) * 8) * 2;
    uint32_t b_row_off = (uint32_t)(2 * A_MATB) + (uint32_t)((wn * 32 + (li & 7)) * GSTRIDE) * 2;
    uint32_t b_col_off = (uint32_t)((li >> 3) * 8) * 2;

    for (int ch = 0; ch < NCH; ch++) {
        uint32_t sb = sbase0 + (ch & 1) * STAGEB;
        if (ch + 2 < NCH) ldA(ch + 2);       // LDG early; latency under MMAs
#pragma unroll
        for (int k16 = 0; k16 < 2; k16++) {
            uint32_t kofs = (uint32_t)(k16 * 16) * 2;
            uint32_t bb[4][2];
#pragma unroll
            for (int nf = 0; nf < 4; nf++) {
                uint32_t addr = sb + b_row_off
                              + (uint32_t)(nf * 8 * GSTRIDE * 2) + kofs + b_col_off;
                ldmx2(bb[nf], addr);
            }
#pragma unroll
            for (int mf = 0; mf < 4; mf++) {
                uint32_t addr = sb + a_row_off
                              + (uint32_t)(mf * 16 * GSTRIDE * 2) + kofs + a_col_off;
                uint32_t ah[4], al[4];
                ldmx4(ah, addr);
                ldmx4(al, addr + A_MATB);
#pragma unroll
                for (int nf = 0; nf < 4; nf++) {
                    mma_fp16(acc[mf][nf], ah, bb[nf][0], bb[nf][1]);
                    mma_fp16(acc[mf][nf], al, bb[nf][0], bb[nf][1]);
                }
            }
        }
        __syncthreads();
        if (ch + 2 < NCH) { stsA(ch & 1); ldB(ch + 2, ch & 1); CP_COMMIT(); }
        if (ch + 1 < NCH) {
            if (ch + 2 < NCH) { CP_WAIT(1); } else { CP_WAIT(0); }
            __syncthreads();
        }
    }

    // epilogue: plane = blockIdx.x; planes 0,1 -> hi/lo, planes 2..5 -> single
    int plane = blockIdx.x;
    size_t base = (size_t)plane * MTOT * 128;
#pragma unroll
    for (int mf = 0; mf < 4; mf++) {
        int r0 = m0 + wm * 64 + mf * 16 + (lane >> 2);
        int r1 = r0 + 8;
#pragma unroll
        for (int nf = 0; nf < 4; nf++) {
            int cp = wn * 32 + nf * 8 + (lane & 3) * 2;
            float b0 = __ldg(bias + n0 + cp);
            float b1 = __ldg(bias + n0 + cp + 1);
            float v00 = acc[mf][nf][0] + b0, v01 = acc[mf][nf][1] + b1;
            float v10 = acc[mf][nf][2] + b0, v11 = acc[mf][nf][3] + b1;
            if (plane < 2) {
                uint32_t w0h, w0l, w1h, w1l;
                split2h(v00, v01, w0h, w0l);
                split2h(v10, v11, w1h, w1l);
                *(uint32_t*)(g_QKVh + base + (size_t)r0 * 128 + cp) = w0h;
                *(uint32_t*)(g_QKVl + base + (size_t)r0 * 128 + cp) = w0l;
                *(uint32_t*)(g_QKVh + base + (size_t)r1 * 128 + cp) = w1h;
                *(uint32_t*)(g_QKVl + base + (size_t)r1 * 128 + cp) = w1l;
            } else {
                *(uint32_t*)(g_QKVh + base + (size_t)r0 * 128 + cp) = pack_h2(v00, v01);
                *(uint32_t*)(g_QKVh + base + (size_t)r1 * 128 + cp) = pack_h2(v10, v11);
            }
        }
    }
}

// ---------------------------------------------------------------------------
// Output GEMM: out[16384,256] = At @ Wo^T + b. A = g_Ath/g_Atl fp16 hi/lo
// (cp.async), B = g_Wo. Grid (2, 128): blockIdx.x = output half.
// ---------------------------------------------------------------------------
__global__ __launch_bounds__(256, 2) void gemm_out(
    const __half* __restrict__ Ah, const __half* __restrict__ Al,
    const __half* __restrict__ B,
    const float* __restrict__ bias, float* __restrict__ Cout)
{
    constexpr int NCH = 8;    // 256 / 32

    extern __shared__ __align__(128) char smc[];
    uint32_t sbase0 = smem_to_u32(smc);

    int tid  = threadIdx.x;
    int warp = tid >> 5, lane = tid & 31;
    int wm = warp & 1;
    int wn = warp >> 1;
    int m0 = blockIdx.y * 128;
    int n0 = blockIdx.x * 128;

    auto load_stage = [&](int ch, int buf) {
        int k0 = ch * 32;
        uint32_t sb = sbase0 + buf * STAGEB;
#pragma unroll
        for (int i = 0; i < 2; i++) {
            int e = tid + i * 256;           // A: 128 rows x 4 chunks
            int r = e >> 2, seg = e & 3;
            uint32_t off = (uint32_t)(r * GSTRIDE + seg * 8) * 2;
            size_t ga = (size_t)(m0 + r) * 256 + k0 + seg * 8;
            cp16(sb + off,          Ah + ga);
            cp16(sb + A_MATB + off, Al + ga);
            size_t gb = (size_t)(n0 + r) * 256 + k0 + seg * 8;
            cp16(sb + 2 * A_MATB + off, B + gb);
        }
    };

    float acc[4][4][4];
#pragma unroll
    for (int mf = 0; mf < 4; mf++)
#pragma unroll
        for (int nf = 0; nf < 4; nf++)
#pragma unroll
            for (int j = 0; j < 4; j++) acc[mf][nf][j] = 0.f;

    load_stage(0, 0); CP_COMMIT();
    load_stage(1, 1); CP_COMMIT();
    CP_WAIT(1);
    __syncthreads();

    int li = lane & 15;
    uint32_t a_row_off = (uint32_t)((wm * 64 + li) * GSTRIDE) * 2;
    uint32_t a_col_off = (uint32_t)((lane >> 4) * 8) * 2;
    uint32_t b_row_off = (uint32_t)(2 * A_MATB) + (uint32_t)((wn * 32 + (li & 7)) * GSTRIDE) * 2;
    uint32_t b_col_off = (uint32_t)((li >> 3) * 8) * 2;

    for (int ch = 0; ch < NCH; ch++) {
        uint32_t sb = sbase0 + (ch & 1) * STAGEB;
#pragma unroll
        for (int k16 = 0; k16 < 2; k16++) {
            uint32_t kofs = (uint32_t)(k16 * 16) * 2;
            uint32_t bb[4][2];
#pragma unroll
            for (int nf = 0; nf < 4; nf++) {
                uint32_t addr = sb + b_row_off
                              + (uint32_t)(nf * 8 * GSTRIDE * 2) + kofs + b_col_off;
                ldmx2(bb[nf], addr);
            }
#pragma unroll
            for (int mf = 0; mf < 4; mf++) {
                uint32_t addr = sb + a_row_off
                              + (uint32_t)(mf * 16 * GSTRIDE * 2) + kofs + a_col_off;
                uint32_t ah[4], al[4];
                ldmx4(ah, addr);
                ldmx4(al, addr + A_MATB);
#pragma unroll
                for (int nf = 0; nf < 4; nf++) {
                    mma_fp16(acc[mf][nf], ah, bb[nf][0], bb[nf][1]);
                    mma_fp16(acc[mf][nf], al, bb[nf][0], bb[nf][1]);
                }
            }
        }
        __syncthreads();
        if (ch + 2 < NCH) { load_stage(ch + 2, ch & 1); CP_COMMIT(); }
        if (ch + 1 < NCH) {
            if (ch + 2 < NCH) { CP_WAIT(1); } else { CP_WAIT(0); }
            __syncthreads();
        }
    }

    float* dst = Cout + (size_t)blockIdx.x * MTOT * 128;
#pragma unroll
    for (int mf = 0; mf < 4; mf++) {
        int r0 = m0 + wm * 64 + mf * 16 + (lane >> 2);
        int r1 = r0 + 8;
#pragma unroll
        for (int nf = 0; nf < 4; nf++) {
            int cp = wn * 32 + nf * 8 + (lane & 3) * 2;
            float b0 = __ldg(bias + n0 + cp);
            float b1 = __ldg(bias + n0 + cp + 1);
            *(float2*)(dst + (size_t)r0 * 128 + cp) =
                make_float2(acc[mf][nf][0] + b0, acc[mf][nf][1] + b1);
            *(float2*)(dst + (size_t)r1 * 128 + cp) =
                make_float2(acc[mf][nf][2] + b0, acc[mf][nf][3] + b1);
        }
    }
}

// ---------------------------------------------------------------------------
// HMMA block-sparse flash attention, fp16 2-term (unchanged).
// Grid (NBQ, 2, BQ); 128 threads; 2 CTAs/SM; double-buffered K/V.
// ---------------------------------------------------------------------------
#define AST   136
#define AMATB (64 * AST * 2)            // 17408 bytes per 64x128 matrix
#define ATT_SMEM (6 * AMATB)            // 104448

__global__ __launch_bounds__(128, 2) void attn_mma()
{
    extern __shared__ __align__(128) char sma[];
    uint32_t sb = smem_to_u32(sma);

    int tid  = threadIdx.x;
    int warp = tid >> 5, lane = tid & 31;
    int qb   = blockIdx.x;
    int part = blockIdx.y;
    int b    = blockIdx.z;

    const __half* Qh = g_QKVh + (size_t)(0 + part) * MTOT * 128;
    const __half* Ql = g_QKVl + (size_t)(0 + part) * MTOT * 128;
    const __half* Kp = g_QKVh + (size_t)(2 + part) * MTOT * 128;
    const __half* Vp = g_QKVh + (size_t)(4 + part) * MTOT * 128;

    int qrow0 = b * LQ + qb * 64;
    const float SC = 0.08838834764831845f * 1.4426950408889634f;

    auto load_q = [&]() {
#pragma unroll
        for (int i = 0; i < 16; i++) {
            int e = tid + i * 128;
            int mat = e >> 10;
            int idx = e & 1023;
            int r = idx >> 4, c = idx & 15;
            const __half* src = (mat ? Ql : Qh) + (size_t)(qrow0 + r) * 128 + c * 8;
            cp16(sb + (uint32_t)(mat * AMATB) + (uint32_t)(r * AST + c * 8) * 2, src);
        }
    };
    auto load_kv = [&](int kb, int s) {
        int krow0 = b * LQ + kb * 64;
        uint32_t stb = sb + (uint32_t)((2 + 2 * s) * AMATB);
#pragma unroll
        for (int i = 0; i < 16; i++) {
            int e = tid + i * 128;
            int mat = e >> 10;
            int idx = e & 1023;
            int r = idx >> 4, c = idx & 15;
            const __half* src = (mat ? Vp : Kp) + (size_t)(krow0 + r) * 128 + c * 8;
            cp16(stb + (uint32_t)(mat * AMATB) + (uint32_t)(r * AST + c * 8) * 2, src);
        }
    };

    float O[16][4];
#pragma unroll
    for (int nf = 0; nf < 16; nf++)
#pragma unroll
        for (int j = 0; j < 4; j++) O[nf][j] = 0.f;
    float m2_0 = -1e30f, m2_1 = -1e30f;
    float l0 = 0.f, l1 = 0.f;

    int cnt = g_cnt[qb];
    const int* list = g_list[qb];

    load_q(); load_kv(list[0], 0); CP_COMMIT();
    if (cnt > 1) { load_kv(list[1], 1); CP_COMMIT(); }
    if (cnt > 1) { CP_WAIT(1); } else { CP_WAIT(0); }
    __syncthreads();

    int li = lane & 15;
    uint32_t a_off  = (uint32_t)((warp * 16 + li) * AST + (lane >> 4) * 8) * 2;
    uint32_t kv_row = (uint32_t)(li * AST + (lane >> 4) * 8) * 2;

    for (int i = 0; i < cnt; i++) {
        int s = i & 1;
        uint32_t sK = sb + (uint32_t)((2 + 2 * s) * AMATB);
        uint32_t sV = sK + AMATB;

        float sv[8][4];
#pragma unroll
        for (int nf = 0; nf < 8; nf++)
#pragma unroll
            for (int j = 0; j < 4; j++) sv[nf][j] = 0.f;

#pragma unroll
        for (int kd = 0; kd < 8; kd++) {
            uint32_t qaddr = sb + a_off + (uint32_t)(kd * 16) * 2;
            uint32_t aH[4], aL[4];
            ldmx4(aH, qaddr);
            ldmx4(aL, qaddr + AMATB);
#pragma unroll
            for (int jg = 0; jg < 4; jg++) {
                uint32_t kaddr = sK + kv_row
                               + (uint32_t)(jg * 16 * AST + kd * 16) * 2;
                uint32_t bK[4];
                ldmx4(bK, kaddr);
                mma_fp16(sv[jg * 2],     aH, bK[0], bK[2]);
                mma_fp16(sv[jg * 2],     aL, bK[0], bK[2]);
                mma_fp16(sv[jg * 2 + 1], aH, bK[1], bK[3]);
                mma_fp16(sv[jg * 2 + 1], aL, bK[1], bK[3]);
            }
        }

        float mx0 = -1e30f, mx1 = -1e30f;
#pragma unroll
        for (int nf = 0; nf < 8; nf++) {
#pragma unroll
            for (int j = 0; j < 4; j++) sv[nf][j] *= SC;
            mx0 = fmaxf(mx0, fmaxf(sv[nf][0], sv[nf][1]));
            mx1 = fmaxf(mx1, fmaxf(sv[nf][2], sv[nf][3]));
        }
        mx0 = fmaxf(mx0, __shfl_xor_sync(0xffffffffu, mx0, 1));
        mx0 = fmaxf(mx0, __shfl_xor_sync(0xffffffffu, mx0, 2));
        mx1 = fmaxf(mx1, __shfl_xor_sync(0xffffffffu, mx1, 1));
        mx1 = fmaxf(mx1, __shfl_xor_sync(0xffffffffu, mx1, 2));

        float m0n = fmaxf(m2_0, mx0);
        float m1n = fmaxf(m2_1, mx1);
        float cor0 = exp2f(m2_0 - m0n);
        float cor1 = exp2f(m2_1 - m1n);
        m2_0 = m0n; m2_1 = m1n;

        uint32_t ph[8][2], pl[8][2];
        float ls0 = 0.f, ls1 = 0.f;
#pragma unroll
        for (int nf = 0; nf < 8; nf++) {
            float p0 = exp2f(sv[nf][0] - m0n);
            float p1 = exp2f(sv[nf][1] - m0n);
            float p2 = exp2f(sv[nf][2] - m1n);
            float p3 = exp2f(sv[nf][3] - m1n);
            ls0 += p0 + p1; ls1 += p2 + p3;
            split2h(p0, p1, ph[nf][0], pl[nf][0]);
            split2h(p2, p3, ph[nf][1], pl[nf][1]);
        }
        ls0 += __shfl_xor_sync(0xffffffffu, ls0, 1);
        ls0 += __shfl_xor_sync(0xffffffffu, ls0, 2);
        ls1 += __shfl_xor_sync(0xffffffffu, ls1, 1);
        ls1 += __shfl_xor_sync(0xffffffffu, ls1, 2);
        l0 = l0 * cor0 + ls0;
        l1 = l1 * cor1 + ls1;

#pragma unroll
        for (int nf = 0; nf < 16; nf++) {
            O[nf][0] *= cor0; O[nf][1] *= cor0;
            O[nf][2] *= cor1; O[nf][3] *= cor1;
        }

#pragma unroll
        for (int kk = 0; kk < 4; kk++) {
            uint32_t aH[4] = {ph[2*kk][0], ph[2*kk][1], ph[2*kk+1][0], ph[2*kk+1][1]};
            uint32_t aL[4] = {pl[2*kk][0], pl[2*kk][1], pl[2*kk+1][0], pl[2*kk+1][1]};
#pragma unroll
            for (int dg = 0; dg < 8; dg++) {
                uint32_t vaddr = sV + kv_row
                               + (uint32_t)(kk * 16 * AST + dg * 16) * 2;
                uint32_t vV[4];
                ldmx4t(vV, vaddr);
                mma_fp16(O[dg * 2],     aH, vV[0], vV[1]);
                mma_fp16(O[dg * 2],     aL, vV[0], vV[1]);
                mma_fp16(O[dg * 2 + 1], aH, vV[2], vV[3]);
                mma_fp16(O[dg * 2 + 1], aL, vV[2], vV[3]);
            }
        }

        __syncthreads();
        if (i + 2 < cnt) { load_kv(list[i + 2], s); CP_COMMIT(); }
        if (i + 1 < cnt) {
            if (i + 2 < cnt) { CP_WAIT(1); } else { CP_WAIT(0); }
            __syncthreads();
        }
    }

    float inv0 = 1.f / l0, inv1 = 1.f / l1;
    int r0 = qrow0 + warp * 16 + (lane >> 2);
    int r1 = r0 + 8;
#pragma unroll
    for (int nf = 0; nf < 16; nf++) {
        int col = part * 128 + nf * 8 + (lane & 3) * 2;
        uint32_t wh, wl;
        split2h(O[nf][0] * inv0, O[nf][1] * inv0, wh, wl);
        *(uint32_t*)(g_Ath + (size_t)r0 * 256 + col) = wh;
        *(uint32_t*)(g_Atl + (size_t)r0 * 256 + col) = wl;
        split2h(O[nf][2] * inv1, O[nf][3] * inv1, wh, wl);
        *(uint32_t*)(g_Ath + (size_t)r1 * 256 + col) = wh;
        *(uint32_t*)(g_Atl + (size_t)r1 * 256 + col) = wl;
    }
}

// ---------------------------------------------------------------------------
// Launch
// ---------------------------------------------------------------------------
extern "C" void kernel_launch(void* const* d_in, const int* in_sizes, int n_in,
                              void* d_out, int out_size)
{
    const float* xin[6];
    for (int i = 0; i < 6; i++) xin[i] = (const float*)d_in[i];
    const float* W_qkv  = (const float*)d_in[6];
    const float* b_qkv  = (const float*)d_in[7];
    const float* W_out  = (const float*)d_in[8];
    const float* b_out  = (const float*)d_in[9];
    const void*  mask   = d_in[10];
    float* out = (float*)d_out;
    (void)in_sizes; (void)n_in; (void)out_size;

    cudaFuncSetAttribute(attn_mma, cudaFuncAttributeMaxDynamicSharedMemorySize,
                         ATT_SMEM);
    cudaFuncSetAttribute(gemm_qkv, cudaFuncAttributeMaxDynamicSharedMemorySize,
                         GEMM_SMEM);
    cudaFuncSetAttribute(gemm_out, cudaFuncAttributeMaxDynamicSharedMemorySize,
                         GEMM_SMEM);

    __half *Wq, *Ath, *Atl, *Wo;
    cudaGetSymbolAddress((void**)&Wq,  g_Wq);
    cudaGetSymbolAddress((void**)&Ath, g_Ath);
    cudaGetSymbolAddress((void**)&Atl, g_Atl);
    cudaGetSymbolAddress((void**)&Wo,  g_Wo);

    build_mask_kernel<<<1, NBQ>>>(mask);                                  // 0
    cvt_kernel<<<(768 * 768 / 4 + 255) / 256, 256>>>((const float4*)W_qkv,
        (uint2*)Wq, 768 * 768 / 4);                                       // 1
    cvt_kernel<<<(256 * 256 / 4 + 255) / 256, 256>>>((const float4*)W_out,
        (uint2*)Wo, 256 * 256 / 4);                                       // 2
    gemm_qkv<<<dim3(6, MTOT / 128), 256, GEMM_SMEM>>>(                    // 3
        xin[0], xin[1], xin[2], xin[3], xin[4], xin[5], Wq, b_qkv);
    attn_mma<<<dim3(NBQ, 2, BQ), 128, ATT_SMEM>>>();                      // 4
    gemm_out<<<dim3(2, MTOT / 128), 256, GEMM_SMEM>>>(                    // 5 <- ncu
        Ath, Atl, Wo, b_out, out);
}

// round 12
// speedup vs baseline: 1.4383x; 1.4383x over previous
#include <cuda_runtime.h>
#include <cuda_fp16.h>
#include <math_constants.h>
#include <cstdint>

// Problem constants
#define BQ   4
#define LQ   4096
#define DQ   128
#define NBQ  64
#define MTOT (BQ * LQ)     // 16384 rows

// ---------------------------------------------------------------------------
// Scratch (__device__ globals; no allocations allowed)
// A-side operands fp16 hi/lo (exact to ~2^-22); B-side single fp16.
// ---------------------------------------------------------------------------
__device__ __half g_Wq[768 * 768];           // W_qkv, single fp16 (B operand)
__device__ __half g_QKVh[6 * MTOT * DQ];     // Q planes: hi; K/V planes: single
__device__ __half g_QKVl[6 * MTOT * DQ];     // Q planes: lo (K/V region unused)
__device__ __half g_Ath[MTOT * 256];         // attention out hi/lo (A operand)
__device__ __half g_Atl[MTOT * 256];
__device__ __half g_Wo[256 * 256];           // W_out, single fp16
__device__ int g_cnt[NBQ];
__device__ int g_list[NBQ][NBQ];

// ---------------------------------------------------------------------------
// Helpers
// ---------------------------------------------------------------------------
__device__ __forceinline__ uint32_t smem_to_u32(const void* p) {
    uint32_t a;
    asm("{ .reg .u64 t; cvta.to.shared.u64 t, %1; cvt.u32.u64 %0, t; }" : "=r"(a) : "l"(p));
    return a;
}
__device__ __forceinline__ void cp16(uint32_t dst_smem, const void* src) {
    asm volatile("cp.async.cg.shared.global [%0], [%1], 16;" :: "r"(dst_smem), "l"(src));
}
#define CP_COMMIT() asm volatile("cp.async.commit_group;" ::: "memory")
#define CP_WAIT(n)  asm volatile("cp.async.wait_group %0;" :: "n"(n) : "memory")

__device__ __forceinline__ void ldmx4(uint32_t* r, uint32_t addr) {
    asm volatile("ldmatrix.sync.aligned.m8n8.x4.shared.b16 {%0,%1,%2,%3}, [%4];"
                 : "=r"(r[0]), "=r"(r[1]), "=r"(r[2]), "=r"(r[3]) : "r"(addr));
}
__device__ __forceinline__ void ldmx4t(uint32_t* r, uint32_t addr) {
    asm volatile("ldmatrix.sync.aligned.m8n8.x4.trans.shared.b16 {%0,%1,%2,%3}, [%4];"
                 : "=r"(r[0]), "=r"(r[1]), "=r"(r[2]), "=r"(r[3]) : "r"(addr));
}
__device__ __forceinline__ void ldmx2(uint32_t* r, uint32_t addr) {
    asm volatile("ldmatrix.sync.aligned.m8n8.x2.shared.b16 {%0,%1}, [%2];"
                 : "=r"(r[0]), "=r"(r[1]) : "r"(addr));
}
__device__ __forceinline__ void mma_fp16(float* c, const uint32_t* a,
                                         uint32_t b0, uint32_t b1) {
    asm volatile(
        "mma.sync.aligned.m16n8k16.row.col.f32.f16.f16.f32 "
        "{%0,%1,%2,%3}, {%4,%5,%6,%7}, {%8,%9}, {%0,%1,%2,%3};"
        : "+f"(c[0]), "+f"(c[1]), "+f"(c[2]), "+f"(c[3])
        : "r"(a[0]), "r"(a[1]), "r"(a[2]), "r"(a[3]), "r"(b0), "r"(b1));
}
__device__ __forceinline__ uint32_t pack_h2(float a, float b) {
    __half2 t = __floats2half2_rn(a, b);
    return *(uint32_t*)&t;
}
__device__ __forceinline__ void split2h(float a, float b, uint32_t& h, uint32_t& l) {
    __half ha = __float2half_rn(a);
    __half hb = __float2half_rn(b);
    h = ((uint32_t)__half_as_ushort(hb) << 16) | __half_as_ushort(ha);
    l = pack_h2(a - __half2float(ha), b - __half2float(hb));
}

// ---------------------------------------------------------------------------
// Block-mask compaction (per-qblock lists)
// ---------------------------------------------------------------------------
__global__ void build_mask_kernel(const void* __restrict__ mask)
{
    int qb = threadIdx.x;
    if (qb >= NBQ) return;
    const float* mf = (const float*)mask;
    const int*   mi = (const int*)mask;
    const unsigned char* mb = (const unsigned char*)mask;
    int mode;
    if (mf[0] == 1.0f)   mode = 0;
    else if (mi[0] == 1) mode = 1;
    else                 mode = 2;
    int cnt = 0;
    for (int kb = 0; kb <= qb; kb++) {
        size_t idx = (size_t)(qb * 64) * (size_t)LQ + (size_t)(kb * 64);
        bool on;
        if (mode == 0)      on = (mf[idx] != 0.0f);
        else if (mode == 1) on = (mi[idx] != 0);
        else                on = (mb[idx] != 0);
        if (on) g_list[qb][cnt++] = kb;
    }
    g_cnt[qb] = cnt;
}

// fp32 -> single fp16 (weights, B operand)
__global__ void cvt_kernel(const float4* __restrict__ src,
                           uint2* __restrict__ dst, int n4)
{
    int i = blockIdx.x * 256 + threadIdx.x;
    if (i >= n4) return;
    float4 v = src[i];
    dst[i] = make_uint2(pack_h2(v.x, v.y), pack_h2(v.z, v.w));
}

// ---------------------------------------------------------------------------
// GEMM geometry: CTA tile 128(M) x 256(N) x 32(K), 512 threads = 16 warps
// in a 4M x 4N grid; warp tile 32x64 (acc[2][8][4] = 64 regs).
// smem rows stride 40 fp16 (80B, conflict-free ldmatrix).
// ---------------------------------------------------------------------------
#define GSTRIDE 40
#define A_MATB  (128 * GSTRIDE * 2)     // 10240 B per A matrix tile
#define B_MATB  (256 * GSTRIDE * 2)     // 20480 B per B matrix tile
#define STAGEB  (2 * A_MATB + B_MATB)   // Ah, Al, B = 40960
#define GEMM_SMEM (2 * STAGEB)          // 81920

// ---------------------------------------------------------------------------
// QKV GEMM: Y[16384,768] = X @ Wq^T + b. A = X fp32 (6 planes), converted to
// fp16 hi/lo IN THE LOADER. 2-term: D = Ah@B + Al@B. Grid (3, 128).
// ---------------------------------------------------------------------------
__global__ __launch_bounds__(512, 1) void gemm_qkv(
    const float* __restrict__ x0, const float* __restrict__ x1,
    const float* __restrict__ x2, const float* __restrict__ x3,
    const float* __restrict__ x4, const float* __restrict__ x5,
    const __half* __restrict__ W, const float* __restrict__ bias)
{
    constexpr int NCH = 24;   // 768 / 32

    extern __shared__ __align__(128) char smc[];
    uint32_t sbase0 = smem_to_u32(smc);

    int tid  = threadIdx.x;
    int warp = tid >> 5, lane = tid & 31;
    int wm = warp & 3;          // 0..3 : 32-row slab
    int wn = warp >> 2;         // 0..3 : 64-col slab
    int m0 = blockIdx.y * 128;
    int n0 = blockIdx.x * 256;

    float4 pre[2];   // A prefetch: 8 fp32 per thread (512 thr x 8 = 4096 = tile)

    auto ldA = [&](int ch) {
        int k0 = ch * 32;
        int pl = k0 >> 7, kc = k0 & 127;
        const float* xp = (pl == 0) ? x0 : (pl == 1) ? x1 : (pl == 2) ? x2
                        : (pl == 3) ? x3 : (pl == 4) ? x4 : x5;
        int r = tid >> 2, seg = tid & 3;
        const float* s = xp + (size_t)(m0 + r) * 128 + kc + seg * 8;
        pre[0] = *(const float4*)s;
        pre[1] = *(const float4*)(s + 4);
    };
    auto stsA = [&](int buf) {
        char* base = smc + buf * STAGEB;
        int r = tid >> 2, seg = tid & 3;
        float4 v0 = pre[0], v1 = pre[1];
        uint32_t h[4], l[4];
        split2h(v0.x, v0.y, h[0], l[0]);
        split2h(v0.z, v0.w, h[1], l[1]);
        split2h(v1.x, v1.y, h[2], l[2]);
        split2h(v1.z, v1.w, h[3], l[3]);
        uint32_t off = (uint32_t)(r * GSTRIDE + seg * 8) * 2;
        *(uint4*)(base + off)          = make_uint4(h[0], h[1], h[2], h[3]);
        *(uint4*)(base + A_MATB + off) = make_uint4(l[0], l[1], l[2], l[3]);
    };
    auto ldB = [&](int ch, int buf) {
        int k0 = ch * 32;
        uint32_t sbB = sbase0 + buf * STAGEB + 2 * A_MATB;
#pragma unroll
        for (int i = 0; i < 2; i++) {
            int e = tid + i * 512;           // 0..1023 = 256 rows x 4 chunks
            int r = e >> 2, seg = e & 3;
            size_t gb = (size_t)(n0 + r) * 768 + k0 + seg * 8;
            cp16(sbB + (uint32_t)(r * GSTRIDE + seg * 8) * 2, W + gb);
        }
    };

    float acc[2][8][4];
#pragma unroll
    for (int mf = 0; mf < 2; mf++)
#pragma unroll
        for (int nf = 0; nf < 8; nf++)
#pragma unroll
            for (int j = 0; j < 4; j++) acc[mf][nf][j] = 0.f;

    ldA(0); stsA(0); ldB(0, 0); CP_COMMIT();
    ldA(1); stsA(1); ldB(1, 1); CP_COMMIT();
    CP_WAIT(1);
    __syncthreads();

    int li = lane & 15;
    uint32_t a_row_off = (uint32_t)((wm * 32 + li) * GSTRIDE) * 2;
    uint32_t a_col_off = (uint32_t)((lane >> 4) * 8) * 2;
    uint32_t b_row_off = (uint32_t)(2 * A_MATB) + (uint32_t)((wn * 64 + (li & 7)) * GSTRIDE) * 2;
    uint32_t b_col_off = (uint32_t)((li >> 3) * 8) * 2;

    for (int ch = 0; ch < NCH; ch++) {
        uint32_t sb = sbase0 + (ch & 1) * STAGEB;
        if (ch + 2 < NCH) ldA(ch + 2);       // LDG early; latency under MMAs
#pragma unroll
        for (int k16 = 0; k16 < 2; k16++) {
            uint32_t kofs = (uint32_t)(k16 * 16) * 2;
            uint32_t bb[8][2];
#pragma unroll
            for (int nf = 0; nf < 8; nf++) {
                uint32_t addr = sb + b_row_off
                              + (uint32_t)(nf * 8 * GSTRIDE * 2) + kofs + b_col_off;
                ldmx2(bb[nf], addr);
            }
#pragma unroll
            for (int mf = 0; mf < 2; mf++) {
                uint32_t addr = sb + a_row_off
                              + (uint32_t)(mf * 16 * GSTRIDE * 2) + kofs + a_col_off;
                uint32_t ah[4], al[4];
                ldmx4(ah, addr);
                ldmx4(al, addr + A_MATB);
#pragma unroll
                for (int nf = 0; nf < 8; nf++) {
                    mma_fp16(acc[mf][nf], ah, bb[nf][0], bb[nf][1]);
                    mma_fp16(acc[mf][nf], al, bb[nf][0], bb[nf][1]);
                }
            }
        }
        __syncthreads();
        if (ch + 2 < NCH) { stsA(ch & 1); ldB(ch + 2, ch & 1); CP_COMMIT(); }
        if (ch + 1 < NCH) {
            if (ch + 2 < NCH) { CP_WAIT(1); } else { CP_WAIT(0); }
            __syncthreads();
        }
    }

    // epilogue: per-column plane select; planes 0,1 -> hi/lo, 2..5 -> single
#pragma unroll
    for (int mf = 0; mf < 2; mf++) {
        int r0 = m0 + wm * 32 + mf * 16 + (lane >> 2);
        int r1 = r0 + 8;
#pragma unroll
        for (int nf = 0; nf < 8; nf++) {
            int gcol = n0 + wn * 64 + nf * 8 + (lane & 3) * 2;
            float b0 = __ldg(bias + gcol);
            float b1 = __ldg(bias + gcol + 1);
            float v00 = acc[mf][nf][0] + b0, v01 = acc[mf][nf][1] + b1;
            float v10 = acc[mf][nf][2] + b0, v11 = acc[mf][nf][3] + b1;
            int plane = gcol >> 7, pcol = gcol & 127;
            size_t base = (size_t)plane * MTOT * 128;
            if (plane < 2) {
                uint32_t w0h, w0l, w1h, w1l;
                split2h(v00, v01, w0h, w0l);
                split2h(v10, v11, w1h, w1l);
                *(uint32_t*)(g_QKVh + base + (size_t)r0 * 128 + pcol) = w0h;
                *(uint32_t*)(g_QKVl + base + (size_t)r0 * 128 + pcol) = w0l;
                *(uint32_t*)(g_QKVh + base + (size_t)r1 * 128 + pcol) = w1h;
                *(uint32_t*)(g_QKVl + base + (size_t)r1 * 128 + pcol) = w1l;
            } else {
                *(uint32_t*)(g_QKVh + base + (size_t)r0 * 128 + pcol) = pack_h2(v00, v01);
                *(uint32_t*)(g_QKVh + base + (size_t)r1 * 128 + pcol) = pack_h2(v10, v11);
            }
        }
    }
}

// ---------------------------------------------------------------------------
// Output GEMM: out[16384,256] = At @ Wo^T + b. Grid (1, 128), N tile = 256.
// ---------------------------------------------------------------------------
__global__ __launch_bounds__(512, 1) void gemm_out(
    const __half* __restrict__ Ah, const __half* __restrict__ Al,
    const __half* __restrict__ B,
    const float* __restrict__ bias, float* __restrict__ Cout)
{
    constexpr int NCH = 8;    // 256 / 32

    extern __shared__ __align__(128) char smc[];
    uint32_t sbase0 = smem_to_u32(smc);

    int tid  = threadIdx.x;
    int warp = tid >> 5, lane = tid & 31;
    int wm = warp & 3;
    int wn = warp >> 2;
    int m0 = blockIdx.y * 128;

    auto load_stage = [&](int ch, int buf) {
        int k0 = ch * 32;
        uint32_t sb = sbase0 + buf * STAGEB;
        {
            int r = tid >> 2, seg = tid & 3;     // A: 128 rows x 4 chunks = 512
            uint32_t off = (uint32_t)(r * GSTRIDE + seg * 8) * 2;
            size_t ga = (size_t)(m0 + r) * 256 + k0 + seg * 8;
            cp16(sb + off,          Ah + ga);
            cp16(sb + A_MATB + off, Al + ga);
        }
#pragma unroll
        for (int i = 0; i < 2; i++) {
            int e = tid + i * 512;               // B: 256 rows x 4 chunks = 1024
            int r = e >> 2, seg = e & 3;
            size_t gb = (size_t)r * 256 + k0 + seg * 8;
            cp16(sb + 2 * A_MATB + (uint32_t)(r * GSTRIDE + seg * 8) * 2, B + gb);
        }
    };

    float acc[2][8][4];
#pragma unroll
    for (int mf = 0; mf < 2; mf++)
#pragma unroll
        for (int nf = 0; nf < 8; nf++)
#pragma unroll
            for (int j = 0; j < 4; j++) acc[mf][nf][j] = 0.f;

    load_stage(0, 0); CP_COMMIT();
    load_stage(1, 1); CP_COMMIT();
    CP_WAIT(1);
    __syncthreads();

    int li = lane & 15;
    uint32_t a_row_off = (uint32_t)((wm * 32 + li) * GSTRIDE) * 2;
    uint32_t a_col_off = (uint32_t)((lane >> 4) * 8) * 2;
    uint32_t b_row_off = (uint32_t)(2 * A_MATB) + (uint32_t)((wn * 64 + (li & 7)) * GSTRIDE) * 2;
    uint32_t b_col_off = (uint32_t)((li >> 3) * 8) * 2;

    for (int ch = 0; ch < NCH; ch++) {
        uint32_t sb = sbase0 + (ch & 1) * STAGEB;
#pragma unroll
        for (int k16 = 0; k16 < 2; k16++) {
            uint32_t kofs = (uint32_t)(k16 * 16) * 2;
            uint32_t bb[8][2];
#pragma unroll
            for (int nf = 0; nf < 8; nf++) {
                uint32_t addr = sb + b_row_off
                              + (uint32_t)(nf * 8 * GSTRIDE * 2) + kofs + b_col_off;
                ldmx2(bb[nf], addr);
            }
#pragma unroll
            for (int mf = 0; mf < 2; mf++) {
                uint32_t addr = sb + a_row_off
                              + (uint32_t)(mf * 16 * GSTRIDE * 2) + kofs + a_col_off;
                uint32_t ah[4], al[4];
                ldmx4(ah, addr);
                ldmx4(al, addr + A_MATB);
#pragma unroll
                for (int nf = 0; nf < 8; nf++) {
                    mma_fp16(acc[mf][nf], ah, bb[nf][0], bb[nf][1]);
                    mma_fp16(acc[mf][nf], al, bb[nf][0], bb[nf][1]);
                }
            }
        }
        __syncthreads();
        if (ch + 2 < NCH) { load_stage(ch + 2, ch & 1); CP_COMMIT(); }
        if (ch + 1 < NCH) {
            if (ch + 2 < NCH) { CP_WAIT(1); } else { CP_WAIT(0); }
            __syncthreads();
        }
    }

#pragma unroll
    for (int mf = 0; mf < 2; mf++) {
        int r0 = m0 + wm * 32 + mf * 16 + (lane >> 2);
        int r1 = r0 + 8;
#pragma unroll
        for (int nf = 0; nf < 8; nf++) {
            int gcol = wn * 64 + nf * 8 + (lane & 3) * 2;
            float b0 = __ldg(bias + gcol);
            float b1 = __ldg(bias + gcol + 1);
            int half = gcol >> 7, pcol = gcol & 127;
            float* dst = Cout + (size_t)half * MTOT * 128;
            *(float2*)(dst + (size_t)r0 * 128 + pcol) =
                make_float2(acc[mf][nf][0] + b0, acc[mf][nf][1] + b1);
            *(float2*)(dst + (size_t)r1 * 128 + pcol) =
                make_float2(acc[mf][nf][2] + b0, acc[mf][nf][3] + b1);
        }
    }
}

// ---------------------------------------------------------------------------
// HMMA block-sparse flash attention, fp16 2-term (unchanged from R10).
// Grid (NBQ, 2, BQ); 128 threads; 2 CTAs/SM; double-buffered K/V.
// ---------------------------------------------------------------------------
#define AST   136
#define AMATB (64 * AST * 2)            // 17408 bytes per 64x128 matrix
#define ATT_SMEM (6 * AMATB)            // 104448

__global__ __launch_bounds__(128, 2) void attn_mma()
{
    extern __shared__ __align__(128) char sma[];
    uint32_t sb = smem_to_u32(sma);

    int tid  = threadIdx.x;
    int warp = tid >> 5, lane = tid & 31;
    int qb   = blockIdx.x;
    int part = blockIdx.y;
    int b    = blockIdx.z;

    const __half* Qh = g_QKVh + (size_t)(0 + part) * MTOT * 128;
    const __half* Ql = g_QKVl + (size_t)(0 + part) * MTOT * 128;
    const __half* Kp = g_QKVh + (size_t)(2 + part) * MTOT * 128;
    const __half* Vp = g_QKVh + (size_t)(4 + part) * MTOT * 128;

    int qrow0 = b * LQ + qb * 64;
    const float SC = 0.08838834764831845f * 1.4426950408889634f;

    auto load_q = [&]() {
#pragma unroll
        for (int i = 0; i < 16; i++) {
            int e = tid + i * 128;
            int mat = e >> 10;
            int idx = e & 1023;
            int r = idx >> 4, c = idx & 15;
            const __half* src = (mat ? Ql : Qh) + (size_t)(qrow0 + r) * 128 + c * 8;
            cp16(sb + (uint32_t)(mat * AMATB) + (uint32_t)(r * AST + c * 8) * 2, src);
        }
    };
    auto load_kv = [&](int kb, int s) {
        int krow0 = b * LQ + kb * 64;
        uint32_t stb = sb + (uint32_t)((2 + 2 * s) * AMATB);
#pragma unroll
        for (int i = 0; i < 16; i++) {
            int e = tid + i * 128;
            int mat = e >> 10;
            int idx = e & 1023;
            int r = idx >> 4, c = idx & 15;
            const __half* src = (mat ? Vp : Kp) + (size_t)(krow0 + r) * 128 + c * 8;
            cp16(stb + (uint32_t)(mat * AMATB) + (uint32_t)(r * AST + c * 8) * 2, src);
        }
    };

    float O[16][4];
#pragma unroll
    for (int nf = 0; nf < 16; nf++)
#pragma unroll
        for (int j = 0; j < 4; j++) O[nf][j] = 0.f;
    float m2_0 = -1e30f, m2_1 = -1e30f;
    float l0 = 0.f, l1 = 0.f;

    int cnt = g_cnt[qb];
    const int* list = g_list[qb];

    load_q(); load_kv(list[0], 0); CP_COMMIT();
    if (cnt > 1) { load_kv(list[1], 1); CP_COMMIT(); }
    if (cnt > 1) { CP_WAIT(1); } else { CP_WAIT(0); }
    __syncthreads();

    int li = lane & 15;
    uint32_t a_off  = (uint32_t)((warp * 16 + li) * AST + (lane >> 4) * 8) * 2;
    uint32_t kv_row = (uint32_t)(li * AST + (lane >> 4) * 8) * 2;

    for (int i = 0; i < cnt; i++) {
        int s = i & 1;
        uint32_t sK = sb + (uint32_t)((2 + 2 * s) * AMATB);
        uint32_t sV = sK + AMATB;

        float sv[8][4];
#pragma unroll
        for (int nf = 0; nf < 8; nf++)
#pragma unroll
            for (int j = 0; j < 4; j++) sv[nf][j] = 0.f;

#pragma unroll
        for (int kd = 0; kd < 8; kd++) {
            uint32_t qaddr = sb + a_off + (uint32_t)(kd * 16) * 2;
            uint32_t aH[4], aL[4];
            ldmx4(aH, qaddr);
            ldmx4(aL, qaddr + AMATB);
#pragma unroll
            for (int jg = 0; jg < 4; jg++) {
                uint32_t kaddr = sK + kv_row
                               + (uint32_t)(jg * 16 * AST + kd * 16) * 2;
                uint32_t bK[4];
                ldmx4(bK, kaddr);
                mma_fp16(sv[jg * 2],     aH, bK[0], bK[2]);
                mma_fp16(sv[jg * 2],     aL, bK[0], bK[2]);
                mma_fp16(sv[jg * 2 + 1], aH, bK[1], bK[3]);
                mma_fp16(sv[jg * 2 + 1], aL, bK[1], bK[3]);
            }
        }

        float mx0 = -1e30f, mx1 = -1e30f;
#pragma unroll
        for (int nf = 0; nf < 8; nf++) {
#pragma unroll
            for (int j = 0; j < 4; j++) sv[nf][j] *= SC;
            mx0 = fmaxf(mx0, fmaxf(sv[nf][0], sv[nf][1]));
            mx1 = fmaxf(mx1, fmaxf(sv[nf][2], sv[nf][3]));
        }
        mx0 = fmaxf(mx0, __shfl_xor_sync(0xffffffffu, mx0, 1));
        mx0 = fmaxf(mx0, __shfl_xor_sync(0xffffffffu, mx0, 2));
        mx1 = fmaxf(mx1, __shfl_xor_sync(0xffffffffu, mx1, 1));
        mx1 = fmaxf(mx1, __shfl_xor_sync(0xffffffffu, mx1, 2));

        float m0n = fmaxf(m2_0, mx0);
        float m1n = fmaxf(m2_1, mx1);
        float cor0 = exp2f(m2_0 - m0n);
        float cor1 = exp2f(m2_1 - m1n);
        m2_0 = m0n; m2_1 = m1n;

        uint32_t ph[8][2], pl[8][2];
        float ls0 = 0.f, ls1 = 0.f;
#pragma unroll
        for (int nf = 0; nf < 8; nf++) {
            float p0 = exp2f(sv[nf][0] - m0n);
            float p1 = exp2f(sv[nf][1] - m0n);
            float p2 = exp2f(sv[nf][2] - m1n);
            float p3 = exp2f(sv[nf][3] - m1n);
            ls0 += p0 + p1; ls1 += p2 + p3;
            split2h(p0, p1, ph[nf][0], pl[nf][0]);
            split2h(p2, p3, ph[nf][1], pl[nf][1]);
        }
        ls0 += __shfl_xor_sync(0xffffffffu, ls0, 1);
        ls0 += __shfl_xor_sync(0xffffffffu, ls0, 2);
        ls1 += __shfl_xor_sync(0xffffffffu, ls1, 1);
        ls1 += __shfl_xor_sync(0xffffffffu, ls1, 2);
        l0 = l0 * cor0 + ls0;
        l1 = l1 * cor1 + ls1;

#pragma unroll
        for (int nf = 0; nf < 16; nf++) {
            O[nf][0] *= cor0; O[nf][1] *= cor0;
            O[nf][2] *= cor1; O[nf][3] *= cor1;
        }

#pragma unroll
        for (int kk = 0; kk < 4; kk++) {
            uint32_t aH[4] = {ph[2*kk][0], ph[2*kk][1], ph[2*kk+1][0], ph[2*kk+1][1]};
            uint32_t aL[4] = {pl[2*kk][0], pl[2*kk][1], pl[2*kk+1][0], pl[2*kk+1][1]};
#pragma unroll
            for (int dg = 0; dg < 8; dg++) {
                uint32_t vaddr = sV + kv_row
                               + (uint32_t)(kk * 16 * AST + dg * 16) * 2;
                uint32_t vV[4];
                ldmx4t(vV, vaddr);
                mma_fp16(O[dg * 2],     aH, vV[0], vV[1]);
                mma_fp16(O[dg * 2],     aL, vV[0], vV[1]);
                mma_fp16(O[dg * 2 + 1], aH, vV[2], vV[3]);
                mma_fp16(O[dg * 2 + 1], aL, vV[2], vV[3]);
            }
        }

        __syncthreads();
        if (i + 2 < cnt) { load_kv(list[i + 2], s); CP_COMMIT(); }
        if (i + 1 < cnt) {
            if (i + 2 < cnt) { CP_WAIT(1); } else { CP_WAIT(0); }
            __syncthreads();
        }
    }

    float inv0 = 1.f / l0, inv1 = 1.f / l1;
    int r0 = qrow0 + warp * 16 + (lane >> 2);
    int r1 = r0 + 8;
#pragma unroll
    for (int nf = 0; nf < 16; nf++) {
        int col = part * 128 + nf * 8 + (lane & 3) * 2;
        uint32_t wh, wl;
        split2h(O[nf][0] * inv0, O[nf][1] * inv0, wh, wl);
        *(uint32_t*)(g_Ath + (size_t)r0 * 256 + col) = wh;
        *(uint32_t*)(g_Atl + (size_t)r0 * 256 + col) = wl;
        split2h(O[nf][2] * inv1, O[nf][3] * inv1, wh, wl);
        *(uint32_t*)(g_Ath + (size_t)r1 * 256 + col) = wh;
        *(uint32_t*)(g_Atl + (size_t)r1 * 256 + col) = wl;
    }
}

// ---------------------------------------------------------------------------
// Launch
// ---------------------------------------------------------------------------
extern "C" void kernel_launch(void* const* d_in, const int* in_sizes, int n_in,
                              void* d_out, int out_size)
{
    const float* xin[6];
    for (int i = 0; i < 6; i++) xin[i] = (const float*)d_in[i];
    const float* W_qkv  = (const float*)d_in[6];
    const float* b_qkv  = (const float*)d_in[7];
    const float* W_out  = (const float*)d_in[8];
    const float* b_out  = (const float*)d_in[9];
    const void*  mask   = d_in[10];
    float* out = (float*)d_out;
    (void)in_sizes; (void)n_in; (void)out_size;

    cudaFuncSetAttribute(attn_mma, cudaFuncAttributeMaxDynamicSharedMemorySize,
                         ATT_SMEM);
    cudaFuncSetAttribute(gemm_qkv, cudaFuncAttributeMaxDynamicSharedMemorySize,
                         GEMM_SMEM);
    cudaFuncSetAttribute(gemm_out, cudaFuncAttributeMaxDynamicSharedMemorySize,
                         GEMM_SMEM);

    __half *Wq, *Ath, *Atl, *Wo;
    cudaGetSymbolAddress((void**)&Wq,  g_Wq);
    cudaGetSymbolAddress((void**)&Ath, g_Ath);
    cudaGetSymbolAddress((void**)&Atl, g_Atl);
    cudaGetSymbolAddress((void**)&Wo,  g_Wo);

    build_mask_kernel<<<1, NBQ>>>(mask);                                  // 0
    cvt_kernel<<<(768 * 768 / 4 + 255) / 256, 256>>>((const float4*)W_qkv,
        (uint2*)Wq, 768 * 768 / 4);                                       // 1
    cvt_kernel<<<(256 * 256 / 4 + 255) / 256, 256>>>((const float4*)W_out,
        (uint2*)Wo, 256 * 256 / 4);                                       // 2
    gemm_qkv<<<dim3(3, MTOT / 128), 512, GEMM_SMEM>>>(                    // 3
        xin[0], xin[1], xin[2], xin[3], xin[4], xin[5], Wq, b_qkv);
    attn_mma<<<dim3(NBQ, 2, BQ), 128, ATT_SMEM>>>();                      // 4
    gemm_out<<<dim3(1, MTOT / 128), 512, GEMM_SMEM>>>(                    // 5 <- ncu
        Ath, Atl, Wo, b_out, out);
}

// round 13
// speedup vs baseline: 1.4924x; 1.0376x over previous
#include <cuda_runtime.h>
#include <cuda_fp16.h>
#include <math_constants.h>
#include <cstdint>

// Problem constants
#define BQ   4
#define LQ   4096
#define DQ   128
#define NBQ  64
#define MTOT (BQ * LQ)     // 16384 rows

// ---------------------------------------------------------------------------
// Scratch (__device__ globals; no allocations allowed)
// A-side operands fp16 hi/lo (exact to ~2^-22); B-side single fp16.
// ---------------------------------------------------------------------------
__device__ __half g_Wq[768 * 768];           // W_qkv, single fp16 (B operand)
__device__ __half g_QKVh[6 * MTOT * DQ];     // Q planes: hi; K/V planes: single
__device__ __half g_QKVl[6 * MTOT * DQ];     // Q planes: lo (K/V region unused)
__device__ __half g_Ath[MTOT * 256];         // attention out hi/lo (A operand)
__device__ __half g_Atl[MTOT * 256];
__device__ __half g_Wo[256 * 256];           // W_out, single fp16
__device__ int g_cnt[NBQ];
__device__ int g_list[NBQ][NBQ];

// ---------------------------------------------------------------------------
// Helpers
// ---------------------------------------------------------------------------
__device__ __forceinline__ uint32_t smem_to_u32(const void* p) {
    uint32_t a;
    asm("{ .reg .u64 t; cvta.to.shared.u64 t, %1; cvt.u32.u64 %0, t; }" : "=r"(a) : "l"(p));
    return a;
}
__device__ __forceinline__ void cp16(uint32_t dst_smem, const void* src) {
    asm volatile("cp.async.cg.shared.global [%0], [%1], 16;" :: "r"(dst_smem), "l"(src));
}
#define CP_COMMIT() asm volatile("cp.async.commit_group;" ::: "memory")
#define CP_WAIT(n)  asm volatile("cp.async.wait_group %0;" :: "n"(n) : "memory")

__device__ __forceinline__ void ldmx4(uint32_t* r, uint32_t addr) {
    asm volatile("ldmatrix.sync.aligned.m8n8.x4.shared.b16 {%0,%1,%2,%3}, [%4];"
                 : "=r"(r[0]), "=r"(r[1]), "=r"(r[2]), "=r"(r[3]) : "r"(addr));
}
__device__ __forceinline__ void ldmx4t(uint32_t* r, uint32_t addr) {
    asm volatile("ldmatrix.sync.aligned.m8n8.x4.trans.shared.b16 {%0,%1,%2,%3}, [%4];"
                 : "=r"(r[0]), "=r"(r[1]), "=r"(r[2]), "=r"(r[3]) : "r"(addr));
}
__device__ __forceinline__ void ldmx2(uint32_t* r, uint32_t addr) {
    asm volatile("ldmatrix.sync.aligned.m8n8.x2.shared.b16 {%0,%1}, [%2];"
                 : "=r"(r[0]), "=r"(r[1]) : "r"(addr));
}
__device__ __forceinline__ void mma_fp16(float* c, const uint32_t* a,
                                         uint32_t b0, uint32_t b1) {
    asm volatile(
        "mma.sync.aligned.m16n8k16.row.col.f32.f16.f16.f32 "
        "{%0,%1,%2,%3}, {%4,%5,%6,%7}, {%8,%9}, {%0,%1,%2,%3};"
        : "+f"(c[0]), "+f"(c[1]), "+f"(c[2]), "+f"(c[3])
        : "r"(a[0]), "r"(a[1]), "r"(a[2]), "r"(a[3]), "r"(b0), "r"(b1));
}
__device__ __forceinline__ uint32_t pack_h2(float a, float b) {
    __half2 t = __floats2half2_rn(a, b);
    return *(uint32_t*)&t;
}
__device__ __forceinline__ void split2h(float a, float b, uint32_t& h, uint32_t& l) {
    __half ha = __float2half_rn(a);
    __half hb = __float2half_rn(b);
    h = ((uint32_t)__half_as_ushort(hb) << 16) | __half_as_ushort(ha);
    l = pack_h2(a - __half2float(ha), b - __half2float(hb));
}

// ---------------------------------------------------------------------------
// Fused prep: block-mask compaction + W_qkv cvt + W_out cvt, one launch.
// Grid: [0..575] -> Wq cvt, [576..639] -> Wo cvt, [640] -> mask.
// ---------------------------------------------------------------------------
#define WQ_BLKS 576     // 768*768/4 / 256
#define WO_BLKS 64      // 256*256/4 / 256
__global__ void prep_kernel(const float4* __restrict__ Wq_src,
                            const float4* __restrict__ Wo_src,
                            const void* __restrict__ mask)
{
    int bx = blockIdx.x;
    if (bx < WQ_BLKS) {
        int i = bx * 256 + threadIdx.x;
        float4 v = Wq_src[i];
        ((uint2*)g_Wq)[i] = make_uint2(pack_h2(v.x, v.y), pack_h2(v.z, v.w));
    } else if (bx < WQ_BLKS + WO_BLKS) {
        int i = (bx - WQ_BLKS) * 256 + threadIdx.x;
        float4 v = Wo_src[i];
        ((uint2*)g_Wo)[i] = make_uint2(pack_h2(v.x, v.y), pack_h2(v.z, v.w));
    } else {
        int qb = threadIdx.x;
        if (qb >= NBQ) return;
        const float* mf = (const float*)mask;
        const int*   mi = (const int*)mask;
        const unsigned char* mb = (const unsigned char*)mask;
        int mode;
        if (mf[0] == 1.0f)   mode = 0;
        else if (mi[0] == 1) mode = 1;
        else                 mode = 2;
        int cnt = 0;
        for (int kb = 0; kb <= qb; kb++) {
            size_t idx = (size_t)(qb * 64) * (size_t)LQ + (size_t)(kb * 64);
            bool on;
            if (mode == 0)      on = (mf[idx] != 0.0f);
            else if (mode == 1) on = (mi[idx] != 0);
            else                on = (mb[idx] != 0);
            if (on) g_list[qb][cnt++] = kb;
        }
        g_cnt[qb] = cnt;
    }
}

// ---------------------------------------------------------------------------
// GEMM geometry: CTA tile 128(M) x 256(N) x 32(K), 512 threads = 16 warps
// in a 4M x 4N grid; warp tile 32x64 (acc[2][8][4] = 64 regs).
// smem rows stride 40 fp16 (80B, conflict-free ldmatrix).
// ---------------------------------------------------------------------------
#define GSTRIDE 40
#define A_MATB  (128 * GSTRIDE * 2)     // 10240 B per A matrix tile
#define B_MATB  (256 * GSTRIDE * 2)     // 20480 B per B matrix tile
#define STAGEB  (2 * A_MATB + B_MATB)   // Ah, Al, B = 40960
#define GEMM_SMEM (2 * STAGEB)          // 81920

// ---------------------------------------------------------------------------
// QKV GEMM: Y[16384,768] = X @ Wq^T + b. A = X fp32 (6 planes), converted to
// fp16 hi/lo IN THE LOADER. 2-term: D = Ah@B + Al@B. Grid (3, 128).
// ---------------------------------------------------------------------------
__global__ __launch_bounds__(512, 1) void gemm_qkv(
    const float* __restrict__ x0, const float* __restrict__ x1,
    const float* __restrict__ x2, const float* __restrict__ x3,
    const float* __restrict__ x4, const float* __restrict__ x5,
    const __half* __restrict__ W, const float* __restrict__ bias)
{
    constexpr int NCH = 24;   // 768 / 32

    extern __shared__ __align__(128) char smc[];
    uint32_t sbase0 = smem_to_u32(smc);

    int tid  = threadIdx.x;
    int warp = tid >> 5, lane = tid & 31;
    int wm = warp & 3;          // 0..3 : 32-row slab
    int wn = warp >> 2;         // 0..3 : 64-col slab
    int m0 = blockIdx.y * 128;
    int n0 = blockIdx.x * 256;

    float4 pre[2];

    auto ldA = [&](int ch) {
        int k0 = ch * 32;
        int pl = k0 >> 7, kc = k0 & 127;
        const float* xp = (pl == 0) ? x0 : (pl == 1) ? x1 : (pl == 2) ? x2
                        : (pl == 3) ? x3 : (pl == 4) ? x4 : x5;
        int r = tid >> 2, seg = tid & 3;
        const float* s = xp + (size_t)(m0 + r) * 128 + kc + seg * 8;
        pre[0] = *(const float4*)s;
        pre[1] = *(const float4*)(s + 4);
    };
    auto stsA = [&](int buf) {
        char* base = smc + buf * STAGEB;
        int r = tid >> 2, seg = tid & 3;
        float4 v0 = pre[0], v1 = pre[1];
        uint32_t h[4], l[4];
        split2h(v0.x, v0.y, h[0], l[0]);
        split2h(v0.z, v0.w, h[1], l[1]);
        split2h(v1.x, v1.y, h[2], l[2]);
        split2h(v1.z, v1.w, h[3], l[3]);
        uint32_t off = (uint32_t)(r * GSTRIDE + seg * 8) * 2;
        *(uint4*)(base + off)          = make_uint4(h[0], h[1], h[2], h[3]);
        *(uint4*)(base + A_MATB + off) = make_uint4(l[0], l[1], l[2], l[3]);
    };
    auto ldB = [&](int ch, int buf) {
        int k0 = ch * 32;
        uint32_t sbB = sbase0 + buf * STAGEB + 2 * A_MATB;
#pragma unroll
        for (int i = 0; i < 2; i++) {
            int e = tid + i * 512;
            int r = e >> 2, seg = e & 3;
            size_t gb = (size_t)(n0 + r) * 768 + k0 + seg * 8;
            cp16(sbB + (uint32_t)(r * GSTRIDE + seg * 8) * 2, W + gb);
        }
    };

    float acc[2][8][4];
#pragma unroll
    for (int mf = 0; mf < 2; mf++)
#pragma unroll
        for (int nf = 0; nf < 8; nf++)
#pragma unroll
            for (int j = 0; j < 4; j++) acc[mf][nf][j] = 0.f;

    ldA(0); stsA(0); ldB(0, 0); CP_COMMIT();
    ldA(1); stsA(1); ldB(1, 1); CP_COMMIT();
    CP_WAIT(1);
    __syncthreads();

    int li = lane & 15;
    uint32_t a_row_off = (uint32_t)((wm * 32 + li) * GSTRIDE) * 2;
    uint32_t a_col_off = (uint32_t)((lane >> 4) * 8) * 2;
    uint32_t b_row_off = (uint32_t)(2 * A_MATB) + (uint32_t)((wn * 64 + (li & 7)) * GSTRIDE) * 2;
    uint32_t b_col_off = (uint32_t)((li >> 3) * 8) * 2;

    for (int ch = 0; ch < NCH; ch++) {
        uint32_t sb = sbase0 + (ch & 1) * STAGEB;
        if (ch + 2 < NCH) ldA(ch + 2);
#pragma unroll
        for (int k16 = 0; k16 < 2; k16++) {
            uint32_t kofs = (uint32_t)(k16 * 16) * 2;
            uint32_t bb[8][2];
#pragma unroll
            for (int nf = 0; nf < 8; nf++) {
                uint32_t addr = sb + b_row_off
                              + (uint32_t)(nf * 8 * GSTRIDE * 2) + kofs + b_col_off;
                ldmx2(bb[nf], addr);
            }
#pragma unroll
            for (int mf = 0; mf < 2; mf++) {
                uint32_t addr = sb + a_row_off
                              + (uint32_t)(mf * 16 * GSTRIDE * 2) + kofs + a_col_off;
                uint32_t ah[4], al[4];
                ldmx4(ah, addr);
                ldmx4(al, addr + A_MATB);
#pragma unroll
                for (int nf = 0; nf < 8; nf++) {
                    mma_fp16(acc[mf][nf], ah, bb[nf][0], bb[nf][1]);
                    mma_fp16(acc[mf][nf], al, bb[nf][0], bb[nf][1]);
                }
            }
        }
        __syncthreads();
        if (ch + 2 < NCH) { stsA(ch & 1); ldB(ch + 2, ch & 1); CP_COMMIT(); }
        if (ch + 1 < NCH) {
            if (ch + 2 < NCH) { CP_WAIT(1); } else { CP_WAIT(0); }
            __syncthreads();
        }
    }

#pragma unroll
    for (int mf = 0; mf < 2; mf++) {
        int r0 = m0 + wm * 32 + mf * 16 + (lane >> 2);
        int r1 = r0 + 8;
#pragma unroll
        for (int nf = 0; nf < 8; nf++) {
            int gcol = n0 + wn * 64 + nf * 8 + (lane & 3) * 2;
            float b0 = __ldg(bias + gcol);
            float b1 = __ldg(bias + gcol + 1);
            float v00 = acc[mf][nf][0] + b0, v01 = acc[mf][nf][1] + b1;
            float v10 = acc[mf][nf][2] + b0, v11 = acc[mf][nf][3] + b1;
            int plane = gcol >> 7, pcol = gcol & 127;
            size_t base = (size_t)plane * MTOT * 128;
            if (plane < 2) {
                uint32_t w0h, w0l, w1h, w1l;
                split2h(v00, v01, w0h, w0l);
                split2h(v10, v11, w1h, w1l);
                *(uint32_t*)(g_QKVh + base + (size_t)r0 * 128 + pcol) = w0h;
                *(uint32_t*)(g_QKVl + base + (size_t)r0 * 128 + pcol) = w0l;
                *(uint32_t*)(g_QKVh + base + (size_t)r1 * 128 + pcol) = w1h;
                *(uint32_t*)(g_QKVl + base + (size_t)r1 * 128 + pcol) = w1l;
            } else {
                *(uint32_t*)(g_QKVh + base + (size_t)r0 * 128 + pcol) = pack_h2(v00, v01);
                *(uint32_t*)(g_QKVh + base + (size_t)r1 * 128 + pcol) = pack_h2(v10, v11);
            }
        }
    }
}

// ---------------------------------------------------------------------------
// Output GEMM: out[16384,256] = At @ Wo^T + b. Grid (1, 128), N tile = 256.
// ---------------------------------------------------------------------------
__global__ __launch_bounds__(512, 1) void gemm_out(
    const __half* __restrict__ Ah, const __half* __restrict__ Al,
    const __half* __restrict__ B,
    const float* __restrict__ bias, float* __restrict__ Cout)
{
    constexpr int NCH = 8;    // 256 / 32

    extern __shared__ __align__(128) char smc[];
    uint32_t sbase0 = smem_to_u32(smc);

    int tid  = threadIdx.x;
    int warp = tid >> 5, lane = tid & 31;
    int wm = warp & 3;
    int wn = warp >> 2;
    int m0 = blockIdx.y * 128;

    auto load_stage = [&](int ch, int buf) {
        int k0 = ch * 32;
        uint32_t sb = sbase0 + buf * STAGEB;
        {
            int r = tid >> 2, seg = tid & 3;
            uint32_t off = (uint32_t)(r * GSTRIDE + seg * 8) * 2;
            size_t ga = (size_t)(m0 + r) * 256 + k0 + seg * 8;
            cp16(sb + off,          Ah + ga);
            cp16(sb + A_MATB + off, Al + ga);
        }
#pragma unroll
        for (int i = 0; i < 2; i++) {
            int e = tid + i * 512;
            int r = e >> 2, seg = e & 3;
            size_t gb = (size_t)r * 256 + k0 + seg * 8;
            cp16(sb + 2 * A_MATB + (uint32_t)(r * GSTRIDE + seg * 8) * 2, B + gb);
        }
    };

    float acc[2][8][4];
#pragma unroll
    for (int mf = 0; mf < 2; mf++)
#pragma unroll
        for (int nf = 0; nf < 8; nf++)
#pragma unroll
            for (int j = 0; j < 4; j++) acc[mf][nf][j] = 0.f;

    load_stage(0, 0); CP_COMMIT();
    load_stage(1, 1); CP_COMMIT();
    CP_WAIT(1);
    __syncthreads();

    int li = lane & 15;
    uint32_t a_row_off = (uint32_t)((wm * 32 + li) * GSTRIDE) * 2;
    uint32_t a_col_off = (uint32_t)((lane >> 4) * 8) * 2;
    uint32_t b_row_off = (uint32_t)(2 * A_MATB) + (uint32_t)((wn * 64 + (li & 7)) * GSTRIDE) * 2;
    uint32_t b_col_off = (uint32_t)((li >> 3) * 8) * 2;

    for (int ch = 0; ch < NCH; ch++) {
        uint32_t sb = sbase0 + (ch & 1) * STAGEB;
#pragma unroll
        for (int k16 = 0; k16 < 2; k16++) {
            uint32_t kofs = (uint32_t)(k16 * 16) * 2;
            uint32_t bb[8][2];
#pragma unroll
            for (int nf = 0; nf < 8; nf++) {
                uint32_t addr = sb + b_row_off
                              + (uint32_t)(nf * 8 * GSTRIDE * 2) + kofs + b_col_off;
                ldmx2(bb[nf], addr);
            }
#pragma unroll
            for (int mf = 0; mf < 2; mf++) {
                uint32_t addr = sb + a_row_off
                              + (uint32_t)(mf * 16 * GSTRIDE * 2) + kofs + a_col_off;
                uint32_t ah[4], al[4];
                ldmx4(ah, addr);
                ldmx4(al, addr + A_MATB);
#pragma unroll
                for (int nf = 0; nf < 8; nf++) {
                    mma_fp16(acc[mf][nf], ah, bb[nf][0], bb[nf][1]);
                    mma_fp16(acc[mf][nf], al, bb[nf][0], bb[nf][1]);
                }
            }
        }
        __syncthreads();
        if (ch + 2 < NCH) { load_stage(ch + 2, ch & 1); CP_COMMIT(); }
        if (ch + 1 < NCH) {
            if (ch + 2 < NCH) { CP_WAIT(1); } else { CP_WAIT(0); }
            __syncthreads();
        }
    }

#pragma unroll
    for (int mf = 0; mf < 2; mf++) {
        int r0 = m0 + wm * 32 + mf * 16 + (lane >> 2);
        int r1 = r0 + 8;
#pragma unroll
        for (int nf = 0; nf < 8; nf++) {
            int gcol = wn * 64 + nf * 8 + (lane & 3) * 2;
            float b0 = __ldg(bias + gcol);
            float b1 = __ldg(bias + gcol + 1);
            int half = gcol >> 7, pcol = gcol & 127;
            float* dst = Cout + (size_t)half * MTOT * 128;
            *(float2*)(dst + (size_t)r0 * 128 + pcol) =
                make_float2(acc[mf][nf][0] + b0, acc[mf][nf][1] + b1);
            *(float2*)(dst + (size_t)r1 * 128 + pcol) =
                make_float2(acc[mf][nf][2] + b0, acc[mf][nf][3] + b1);
        }
    }
}

// ---------------------------------------------------------------------------
// HMMA block-sparse flash attention, fp16 2-term.
// Grid (NBQ, 2, BQ); 128 threads; 2 CTAs/SM; double-buffered K/V.
// LPT scheduling: qb = NBQ-1-blockIdx.x so heaviest (causal) blocks start
// in wave 0 and the 1.7-wave grid has a short tail.
// ---------------------------------------------------------------------------
#define AST   136
#define AMATB (64 * AST * 2)            // 17408 bytes per 64x128 matrix
#define ATT_SMEM (6 * AMATB)            // 104448

__global__ __launch_bounds__(128, 2) void attn_mma()
{
    extern __shared__ __align__(128) char sma[];
    uint32_t sb = smem_to_u32(sma);

    int tid  = threadIdx.x;
    int warp = tid >> 5, lane = tid & 31;
    int qb   = NBQ - 1 - blockIdx.x;     // LPT order
    int part = blockIdx.y;
    int b    = blockIdx.z;

    const __half* Qh = g_QKVh + (size_t)(0 + part) * MTOT * 128;
    const __half* Ql = g_QKVl + (size_t)(0 + part) * MTOT * 128;
    const __half* Kp = g_QKVh + (size_t)(2 + part) * MTOT * 128;
    const __half* Vp = g_QKVh + (size_t)(4 + part) * MTOT * 128;

    int qrow0 = b * LQ + qb * 64;
    const float SC = 0.08838834764831845f * 1.4426950408889634f;

    auto load_q = [&]() {
#pragma unroll
        for (int i = 0; i < 16; i++) {
            int e = tid + i * 128;
            int mat = e >> 10;
            int idx = e & 1023;
            int r = idx >> 4, c = idx & 15;
            const __half* src = (mat ? Ql : Qh) + (size_t)(qrow0 + r) * 128 + c * 8;
            cp16(sb + (uint32_t)(mat * AMATB) + (uint32_t)(r * AST + c * 8) * 2, src);
        }
    };
    auto load_kv = [&](int kb, int s) {
        int krow0 = b * LQ + kb * 64;
        uint32_t stb = sb + (uint32_t)((2 + 2 * s) * AMATB);
#pragma unroll
        for (int i = 0; i < 16; i++) {
            int e = tid + i * 128;
            int mat = e >> 10;
            int idx = e & 1023;
            int r = idx >> 4, c = idx & 15;
            const __half* src = (mat ? Vp : Kp) + (size_t)(krow0 + r) * 128 + c * 8;
            cp16(stb + (uint32_t)(mat * AMATB) + (uint32_t)(r * AST + c * 8) * 2, src);
        }
    };

    float O[16][4];
#pragma unroll
    for (int nf = 0; nf < 16; nf++)
#pragma unroll
        for (int j = 0; j < 4; j++) O[nf][j] = 0.f;
    float m2_0 = -1e30f, m2_1 = -1e30f;
    float l0 = 0.f, l1 = 0.f;

    int cnt = g_cnt[qb];
    const int* list = g_list[qb];

    load_q(); load_kv(list[0], 0); CP_COMMIT();
    if (cnt > 1) { load_kv(list[1], 1); CP_COMMIT(); }
    if (cnt > 1) { CP_WAIT(1); } else { CP_WAIT(0); }
    __syncthreads();

    int li = lane & 15;
    uint32_t a_off  = (uint32_t)((warp * 16 + li) * AST + (lane >> 4) * 8) * 2;
    uint32_t kv_row = (uint32_t)(li * AST + (lane >> 4) * 8) * 2;

    for (int i = 0; i < cnt; i++) {
        int s = i & 1;
        uint32_t sK = sb + (uint32_t)((2 + 2 * s) * AMATB);
        uint32_t sV = sK + AMATB;

        float sv[8][4];
#pragma unroll
        for (int nf = 0; nf < 8; nf++)
#pragma unroll
            for (int j = 0; j < 4; j++) sv[nf][j] = 0.f;

#pragma unroll
        for (int kd = 0; kd < 8; kd++) {
            uint32_t qaddr = sb + a_off + (uint32_t)(kd * 16) * 2;
            uint32_t aH[4], aL[4];
            ldmx4(aH, qaddr);
            ldmx4(aL, qaddr + AMATB);
#pragma unroll
            for (int jg = 0; jg < 4; jg++) {
                uint32_t kaddr = sK + kv_row
                               + (uint32_t)(jg * 16 * AST + kd * 16) * 2;
                uint32_t bK[4];
                ldmx4(bK, kaddr);
                mma_fp16(sv[jg * 2],     aH, bK[0], bK[2]);
                mma_fp16(sv[jg * 2],     aL, bK[0], bK[2]);
                mma_fp16(sv[jg * 2 + 1], aH, bK[1], bK[3]);
                mma_fp16(sv[jg * 2 + 1], aL, bK[1], bK[3]);
            }
        }

        float mx0 = -1e30f, mx1 = -1e30f;
#pragma unroll
        for (int nf = 0; nf < 8; nf++) {
#pragma unroll
            for (int j = 0; j < 4; j++) sv[nf][j] *= SC;
            mx0 = fmaxf(mx0, fmaxf(sv[nf][0], sv[nf][1]));
            mx1 = fmaxf(mx1, fmaxf(sv[nf][2], sv[nf][3]));
        }
        mx0 = fmaxf(mx0, __shfl_xor_sync(0xffffffffu, mx0, 1));
        mx0 = fmaxf(mx0, __shfl_xor_sync(0xffffffffu, mx0, 2));
        mx1 = fmaxf(mx1, __shfl_xor_sync(0xffffffffu, mx1, 1));
        mx1 = fmaxf(mx1, __shfl_xor_sync(0xffffffffu, mx1, 2));

        float m0n = fmaxf(m2_0, mx0);
        float m1n = fmaxf(m2_1, mx1);
        float cor0 = exp2f(m2_0 - m0n);
        float cor1 = exp2f(m2_1 - m1n);
        m2_0 = m0n; m2_1 = m1n;

        uint32_t ph[8][2], pl[8][2];
        float ls0 = 0.f, ls1 = 0.f;
#pragma unroll
        for (int nf = 0; nf < 8; nf++) {
            float p0 = exp2f(sv[nf][0] - m0n);
            float p1 = exp2f(sv[nf][1] - m0n);
            float p2 = exp2f(sv[nf][2] - m1n);
            float p3 = exp2f(sv[nf][3] - m1n);
            ls0 += p0 + p1; ls1 += p2 + p3;
            split2h(p0, p1, ph[nf][0], pl[nf][0]);
            split2h(p2, p3, ph[nf][1], pl[nf][1]);
        }
        ls0 += __shfl_xor_sync(0xffffffffu, ls0, 1);
        ls0 += __shfl_xor_sync(0xffffffffu, ls0, 2);
        ls1 += __shfl_xor_sync(0xffffffffu, ls1, 1);
        ls1 += __shfl_xor_sync(0xffffffffu, ls1, 2);
        l0 = l0 * cor0 + ls0;
        l1 = l1 * cor1 + ls1;

#pragma unroll
        for (int nf = 0; nf < 16; nf++) {
            O[nf][0] *= cor0; O[nf][1] *= cor0;
            O[nf][2] *= cor1; O[nf][3] *= cor1;
        }

#pragma unroll
        for (int kk = 0; kk < 4; kk++) {
            uint32_t aH[4] = {ph[2*kk][0], ph[2*kk][1], ph[2*kk+1][0], ph[2*kk+1][1]};
            uint32_t aL[4] = {pl[2*kk][0], pl[2*kk][1], pl[2*kk+1][0], pl[2*kk+1][1]};
#pragma unroll
            for (int dg = 0; dg < 8; dg++) {
                uint32_t vaddr = sV + kv_row
                               + (uint32_t)(kk * 16 * AST + dg * 16) * 2;
                uint32_t vV[4];
                ldmx4t(vV, vaddr);
                mma_fp16(O[dg * 2],     aH, vV[0], vV[1]);
                mma_fp16(O[dg * 2],     aL, vV[0], vV[1]);
                mma_fp16(O[dg * 2 + 1], aH, vV[2], vV[3]);
                mma_fp16(O[dg * 2 + 1], aL, vV[2], vV[3]);
            }
        }

        __syncthreads();
        if (i + 2 < cnt) { load_kv(list[i + 2], s); CP_COMMIT(); }
        if (i + 1 < cnt) {
            if (i + 2 < cnt) { CP_WAIT(1); } else { CP_WAIT(0); }
            __syncthreads();
        }
    }

    float inv0 = 1.f / l0, inv1 = 1.f / l1;
    int r0 = qrow0 + warp * 16 + (lane >> 2);
    int r1 = r0 + 8;
#pragma unroll
    for (int nf = 0; nf < 16; nf++) {
        int col = part * 128 + nf * 8 + (lane & 3) * 2;
        uint32_t wh, wl;
        split2h(O[nf][0] * inv0, O[nf][1] * inv0, wh, wl);
        *(uint32_t*)(g_Ath + (size_t)r0 * 256 + col) = wh;
        *(uint32_t*)(g_Atl + (size_t)r0 * 256 + col) = wl;
        split2h(O[nf][2] * inv1, O[nf][3] * inv1, wh, wl);
        *(uint32_t*)(g_Ath + (size_t)r1 * 256 + col) = wh;
        *(uint32_t*)(g_Atl + (size_t)r1 * 256 + col) = wl;
    }
}

// ---------------------------------------------------------------------------
// Launch
// ---------------------------------------------------------------------------
extern "C" void kernel_launch(void* const* d_in, const int* in_sizes, int n_in,
                              void* d_out, int out_size)
{
    const float* xin[6];
    for (int i = 0; i < 6; i++) xin[i] = (const float*)d_in[i];
    const float* W_qkv  = (const float*)d_in[6];
    const float* b_qkv  = (const float*)d_in[7];
    const float* W_out  = (const float*)d_in[8];
    const float* b_out  = (const float*)d_in[9];
    const void*  mask   = d_in[10];
    float* out = (float*)d_out;
    (void)in_sizes; (void)n_in; (void)out_size;

    cudaFuncSetAttribute(attn_mma, cudaFuncAttributeMaxDynamicSharedMemorySize,
                         ATT_SMEM);
    cudaFuncSetAttribute(gemm_qkv, cudaFuncAttributeMaxDynamicSharedMemorySize,
                         GEMM_SMEM);
    cudaFuncSetAttribute(gemm_out, cudaFuncAttributeMaxDynamicSharedMemorySize,
                         GEMM_SMEM);

    __half *Wq, *Ath, *Atl, *Wo;
    cudaGetSymbolAddress((void**)&Wq,  g_Wq);
    cudaGetSymbolAddress((void**)&Ath, g_Ath);
    cudaGetSymbolAddress((void**)&Atl, g_Atl);
    cudaGetSymbolAddress((void**)&Wo,  g_Wo);

    prep_kernel<<<WQ_BLKS + WO_BLKS + 1, 256>>>(                          // 0
        (const float4*)W_qkv, (const float4*)W_out, mask);
    gemm_qkv<<<dim3(3, MTOT / 128), 512, GEMM_SMEM>>>(                    // 1
        xin[0], xin[1], xin[2], xin[3], xin[4], xin[5], Wq, b_qkv);
    attn_mma<<<dim3(NBQ, 2, BQ), 128, ATT_SMEM>>>();                      // 2
    gemm_out<<<dim3(1, MTOT / 128), 512, GEMM_SMEM>>>(                    // 3
        Ath, Atl, Wo, b_out, out);
}

// round 14
// speedup vs baseline: 1.6446x; 1.1020x over previous
#include <cuda_runtime.h>
#include <cuda_fp16.h>
#include <math_constants.h>
#include <cstdint>

// Problem constants
#define BQ   4
#define LQ   4096
#define DQ   128
#define NBQ  64
#define MTOT (BQ * LQ)     // 16384 rows

// ---------------------------------------------------------------------------
// Scratch (__device__ globals; no allocations allowed)
// ---------------------------------------------------------------------------
__device__ __half g_Wq[768 * 768];           // W_qkv, single fp16 (B operand)
__device__ __half g_QKVh[6 * MTOT * DQ];     // Q planes: hi; K/V planes: single
__device__ __half g_QKVl[6 * MTOT * DQ];     // Q planes: lo (K/V region unused)
__device__ __half g_Ath[MTOT * 256];         // attention out, single fp16
__device__ __half g_Wo[256 * 256];           // W_out, single fp16
__device__ int g_cnt[NBQ];
__device__ int g_list[NBQ][NBQ];

// ---------------------------------------------------------------------------
// Helpers
// ---------------------------------------------------------------------------
__device__ __forceinline__ uint32_t smem_to_u32(const void* p) {
    uint32_t a;
    asm("{ .reg .u64 t; cvta.to.shared.u64 t, %1; cvt.u32.u64 %0, t; }" : "=r"(a) : "l"(p));
    return a;
}
__device__ __forceinline__ void cp16(uint32_t dst_smem, const void* src) {
    asm volatile("cp.async.cg.shared.global [%0], [%1], 16;" :: "r"(dst_smem), "l"(src));
}
#define CP_COMMIT() asm volatile("cp.async.commit_group;" ::: "memory")
#define CP_WAIT(n)  asm volatile("cp.async.wait_group %0;" :: "n"(n) : "memory")

__device__ __forceinline__ void ldmx4(uint32_t* r, uint32_t addr) {
    asm volatile("ldmatrix.sync.aligned.m8n8.x4.shared.b16 {%0,%1,%2,%3}, [%4];"
                 : "=r"(r[0]), "=r"(r[1]), "=r"(r[2]), "=r"(r[3]) : "r"(addr));
}
__device__ __forceinline__ void ldmx4t(uint32_t* r, uint32_t addr) {
    asm volatile("ldmatrix.sync.aligned.m8n8.x4.trans.shared.b16 {%0,%1,%2,%3}, [%4];"
                 : "=r"(r[0]), "=r"(r[1]), "=r"(r[2]), "=r"(r[3]) : "r"(addr));
}
__device__ __forceinline__ void ldmx2(uint32_t* r, uint32_t addr) {
    asm volatile("ldmatrix.sync.aligned.m8n8.x2.shared.b16 {%0,%1}, [%2];"
                 : "=r"(r[0]), "=r"(r[1]) : "r"(addr));
}
__device__ __forceinline__ void mma_fp16(float* c, const uint32_t* a,
                                         uint32_t b0, uint32_t b1) {
    asm volatile(
        "mma.sync.aligned.m16n8k16.row.col.f32.f16.f16.f32 "
        "{%0,%1,%2,%3}, {%4,%5,%6,%7}, {%8,%9}, {%0,%1,%2,%3};"
        : "+f"(c[0]), "+f"(c[1]), "+f"(c[2]), "+f"(c[3])
        : "r"(a[0]), "r"(a[1]), "r"(a[2]), "r"(a[3]), "r"(b0), "r"(b1));
}
__device__ __forceinline__ uint32_t pack_h2(float a, float b) {
    __half2 t = __floats2half2_rn(a, b);
    return *(uint32_t*)&t;
}
__device__ __forceinline__ void split2h(float a, float b, uint32_t& h, uint32_t& l) {
    __half ha = __float2half_rn(a);
    __half hb = __float2half_rn(b);
    h = ((uint32_t)__half_as_ushort(hb) << 16) | __half_as_ushort(ha);
    l = pack_h2(a - __half2float(ha), b - __half2float(hb));
}

// ---------------------------------------------------------------------------
// Fused prep: block-mask compaction + W_qkv cvt + W_out cvt, one launch.
// ---------------------------------------------------------------------------
#define WQ_BLKS 576     // 768*768/4 / 256
#define WO_BLKS 64      // 256*256/4 / 256
__global__ void prep_kernel(const float4* __restrict__ Wq_src,
                            const float4* __restrict__ Wo_src,
                            const void* __restrict__ mask)
{
    int bx = blockIdx.x;
    if (bx < WQ_BLKS) {
        int i = bx * 256 + threadIdx.x;
        float4 v = Wq_src[i];
        ((uint2*)g_Wq)[i] = make_uint2(pack_h2(v.x, v.y), pack_h2(v.z, v.w));
    } else if (bx < WQ_BLKS + WO_BLKS) {
        int i = (bx - WQ_BLKS) * 256 + threadIdx.x;
        float4 v = Wo_src[i];
        ((uint2*)g_Wo)[i] = make_uint2(pack_h2(v.x, v.y), pack_h2(v.z, v.w));
    } else {
        int qb = threadIdx.x;
        if (qb >= NBQ) return;
        const float* mf = (const float*)mask;
        const int*   mi = (const int*)mask;
        const unsigned char* mb = (const unsigned char*)mask;
        int mode;
        if (mf[0] == 1.0f)   mode = 0;
        else if (mi[0] == 1) mode = 1;
        else                 mode = 2;
        int cnt = 0;
        for (int kb = 0; kb <= qb; kb++) {
            size_t idx = (size_t)(qb * 64) * (size_t)LQ + (size_t)(kb * 64);
            bool on;
            if (mode == 0)      on = (mf[idx] != 0.0f);
            else if (mode == 1) on = (mi[idx] != 0);
            else                on = (mb[idx] != 0);
            if (on) g_list[qb][cnt++] = kb;
        }
        g_cnt[qb] = cnt;
    }
}

// ---------------------------------------------------------------------------
// GEMM geometry: CTA tile 128(M) x 256(N) x 32(K), 512 threads = 16 warps
// (4M x 4N); warp tile 32x64. smem rows stride 40 fp16.
// ---------------------------------------------------------------------------
#define GSTRIDE 40
#define A_MATB  (128 * GSTRIDE * 2)     // 10240 B per A matrix tile
#define B_MATB  (256 * GSTRIDE * 2)     // 20480 B per B matrix tile
#define STAGEB  (2 * A_MATB + B_MATB)   // Ah, Al(Q slab only), B = 40960
#define GEMM_SMEM (2 * STAGEB)          // 81920

// ---------------------------------------------------------------------------
// QKV GEMM: Y[16384,768] = X @ Wq^T + b. Grid (3, 128).
// Slab 0 (planes 0,1 = Q): 2-term fp16 (Ah + Al) -> Q output hi/lo exact.
// Slabs 1,2 (planes 2..5 = K,V): 1-term (X single fp16) -> single fp16 out.
// ---------------------------------------------------------------------------
__global__ __launch_bounds__(512, 1) void gemm_qkv(
    const float* __restrict__ x0, const float* __restrict__ x1,
    const float* __restrict__ x2, const float* __restrict__ x3,
    const float* __restrict__ x4, const float* __restrict__ x5,
    const __half* __restrict__ W, const float* __restrict__ bias)
{
    constexpr int NCH = 24;   // 768 / 32

    extern __shared__ __align__(128) char smc[];
    uint32_t sbase0 = smem_to_u32(smc);

    int tid  = threadIdx.x;
    int warp = tid >> 5, lane = tid & 31;
    int wm = warp & 3;
    int wn = warp >> 2;
    int m0 = blockIdx.y * 128;
    int n0 = blockIdx.x * 256;
    const bool useLo = (blockIdx.x == 0);    // Q slab: 2-term

    float4 pre[2];

    auto ldA = [&](int ch) {
        int k0 = ch * 32;
        int pl = k0 >> 7, kc = k0 & 127;
        const float* xp = (pl == 0) ? x0 : (pl == 1) ? x1 : (pl == 2) ? x2
                        : (pl == 3) ? x3 : (pl == 4) ? x4 : x5;
        int r = tid >> 2, seg = tid & 3;
        const float* s = xp + (size_t)(m0 + r) * 128 + kc + seg * 8;
        pre[0] = *(const float4*)s;
        pre[1] = *(const float4*)(s + 4);
    };
    auto stsA = [&](int buf) {
        char* base = smc + buf * STAGEB;
        int r = tid >> 2, seg = tid & 3;
        float4 v0 = pre[0], v1 = pre[1];
        uint32_t h[4], l[4];
        split2h(v0.x, v0.y, h[0], l[0]);
        split2h(v0.z, v0.w, h[1], l[1]);
        split2h(v1.x, v1.y, h[2], l[2]);
        split2h(v1.z, v1.w, h[3], l[3]);
        uint32_t off = (uint32_t)(r * GSTRIDE + seg * 8) * 2;
        *(uint4*)(base + off) = make_uint4(h[0], h[1], h[2], h[3]);
        if (useLo)
            *(uint4*)(base + A_MATB + off) = make_uint4(l[0], l[1], l[2], l[3]);
    };
    auto ldB = [&](int ch, int buf) {
        int k0 = ch * 32;
        uint32_t sbB = sbase0 + buf * STAGEB + 2 * A_MATB;
#pragma unroll
        for (int i = 0; i < 2; i++) {
            int e = tid + i * 512;
            int r = e >> 2, seg = e & 3;
            size_t gb = (size_t)(n0 + r) * 768 + k0 + seg * 8;
            cp16(sbB + (uint32_t)(r * GSTRIDE + seg * 8) * 2, W + gb);
        }
    };

    float acc[2][8][4];
#pragma unroll
    for (int mf = 0; mf < 2; mf++)
#pragma unroll
        for (int nf = 0; nf < 8; nf++)
#pragma unroll
            for (int j = 0; j < 4; j++) acc[mf][nf][j] = 0.f;

    ldA(0); stsA(0); ldB(0, 0); CP_COMMIT();
    ldA(1); stsA(1); ldB(1, 1); CP_COMMIT();
    CP_WAIT(1);
    __syncthreads();

    int li = lane & 15;
    uint32_t a_row_off = (uint32_t)((wm * 32 + li) * GSTRIDE) * 2;
    uint32_t a_col_off = (uint32_t)((lane >> 4) * 8) * 2;
    uint32_t b_row_off = (uint32_t)(2 * A_MATB) + (uint32_t)((wn * 64 + (li & 7)) * GSTRIDE) * 2;
    uint32_t b_col_off = (uint32_t)((li >> 3) * 8) * 2;

    for (int ch = 0; ch < NCH; ch++) {
        uint32_t sb = sbase0 + (ch & 1) * STAGEB;
        if (ch + 2 < NCH) ldA(ch + 2);
#pragma unroll
        for (int k16 = 0; k16 < 2; k16++) {
            uint32_t kofs = (uint32_t)(k16 * 16) * 2;
            uint32_t bb[8][2];
#pragma unroll
            for (int nf = 0; nf < 8; nf++) {
                uint32_t addr = sb + b_row_off
                              + (uint32_t)(nf * 8 * GSTRIDE * 2) + kofs + b_col_off;
                ldmx2(bb[nf], addr);
            }
#pragma unroll
            for (int mf = 0; mf < 2; mf++) {
                uint32_t addr = sb + a_row_off
                              + (uint32_t)(mf * 16 * GSTRIDE * 2) + kofs + a_col_off;
                uint32_t ah[4];
                ldmx4(ah, addr);
#pragma unroll
                for (int nf = 0; nf < 8; nf++)
                    mma_fp16(acc[mf][nf], ah, bb[nf][0], bb[nf][1]);
                if (useLo) {
                    uint32_t al[4];
                    ldmx4(al, addr + A_MATB);
#pragma unroll
                    for (int nf = 0; nf < 8; nf++)
                        mma_fp16(acc[mf][nf], al, bb[nf][0], bb[nf][1]);
                }
            }
        }
        __syncthreads();
        if (ch + 2 < NCH) { stsA(ch & 1); ldB(ch + 2, ch & 1); CP_COMMIT(); }
        if (ch + 1 < NCH) {
            if (ch + 2 < NCH) { CP_WAIT(1); } else { CP_WAIT(0); }
            __syncthreads();
        }
    }

#pragma unroll
    for (int mf = 0; mf < 2; mf++) {
        int r0 = m0 + wm * 32 + mf * 16 + (lane >> 2);
        int r1 = r0 + 8;
#pragma unroll
        for (int nf = 0; nf < 8; nf++) {
            int gcol = n0 + wn * 64 + nf * 8 + (lane & 3) * 2;
            float b0 = __ldg(bias + gcol);
            float b1 = __ldg(bias + gcol + 1);
            float v00 = acc[mf][nf][0] + b0, v01 = acc[mf][nf][1] + b1;
            float v10 = acc[mf][nf][2] + b0, v11 = acc[mf][nf][3] + b1;
            int plane = gcol >> 7, pcol = gcol & 127;
            size_t base = (size_t)plane * MTOT * 128;
            if (plane < 2) {
                uint32_t w0h, w0l, w1h, w1l;
                split2h(v00, v01, w0h, w0l);
                split2h(v10, v11, w1h, w1l);
                *(uint32_t*)(g_QKVh + base + (size_t)r0 * 128 + pcol) = w0h;
                *(uint32_t*)(g_QKVl + base + (size_t)r0 * 128 + pcol) = w0l;
                *(uint32_t*)(g_QKVh + base + (size_t)r1 * 128 + pcol) = w1h;
                *(uint32_t*)(g_QKVl + base + (size_t)r1 * 128 + pcol) = w1l;
            } else {
                *(uint32_t*)(g_QKVh + base + (size_t)r0 * 128 + pcol) = pack_h2(v00, v01);
                *(uint32_t*)(g_QKVh + base + (size_t)r1 * 128 + pcol) = pack_h2(v10, v11);
            }
        }
    }
}

// ---------------------------------------------------------------------------
// Output GEMM (1-term): out[16384,256] = At @ Wo^T + b. Grid (1, 128).
// ---------------------------------------------------------------------------
__global__ __launch_bounds__(512, 1) void gemm_out(
    const __half* __restrict__ Ah, const __half* __restrict__ B,
    const float* __restrict__ bias, float* __restrict__ Cout)
{
    constexpr int NCH = 8;    // 256 / 32

    extern __shared__ __align__(128) char smc[];
    uint32_t sbase0 = smem_to_u32(smc);

    int tid  = threadIdx.x;
    int warp = tid >> 5, lane = tid & 31;
    int wm = warp & 3;
    int wn = warp >> 2;
    int m0 = blockIdx.y * 128;

    auto load_stage = [&](int ch, int buf) {
        int k0 = ch * 32;
        uint32_t sb = sbase0 + buf * STAGEB;
        {
            int r = tid >> 2, seg = tid & 3;
            uint32_t off = (uint32_t)(r * GSTRIDE + seg * 8) * 2;
            size_t ga = (size_t)(m0 + r) * 256 + k0 + seg * 8;
            cp16(sb + off, Ah + ga);
        }
#pragma unroll
        for (int i = 0; i < 2; i++) {
            int e = tid + i * 512;
            int r = e >> 2, seg = e & 3;
            size_t gb = (size_t)r * 256 + k0 + seg * 8;
            cp16(sb + 2 * A_MATB + (uint32_t)(r * GSTRIDE + seg * 8) * 2, B + gb);
        }
    };

    float acc[2][8][4];
#pragma unroll
    for (int mf = 0; mf < 2; mf++)
#pragma unroll
        for (int nf = 0; nf < 8; nf++)
#pragma unroll
            for (int j = 0; j < 4; j++) acc[mf][nf][j] = 0.f;

    load_stage(0, 0); CP_COMMIT();
    load_stage(1, 1); CP_COMMIT();
    CP_WAIT(1);
    __syncthreads();

    int li = lane & 15;
    uint32_t a_row_off = (uint32_t)((wm * 32 + li) * GSTRIDE) * 2;
    uint32_t a_col_off = (uint32_t)((lane >> 4) * 8) * 2;
    uint32_t b_row_off = (uint32_t)(2 * A_MATB) + (uint32_t)((wn * 64 + (li & 7)) * GSTRIDE) * 2;
    uint32_t b_col_off = (uint32_t)((li >> 3) * 8) * 2;

    for (int ch = 0; ch < NCH; ch++) {
        uint32_t sb = sbase0 + (ch & 1) * STAGEB;
#pragma unroll
        for (int k16 = 0; k16 < 2; k16++) {
            uint32_t kofs = (uint32_t)(k16 * 16) * 2;
            uint32_t bb[8][2];
#pragma unroll
            for (int nf = 0; nf < 8; nf++) {
                uint32_t addr = sb + b_row_off
                              + (uint32_t)(nf * 8 * GSTRIDE * 2) + kofs + b_col_off;
                ldmx2(bb[nf], addr);
            }
#pragma unroll
            for (int mf = 0; mf < 2; mf++) {
                uint32_t addr = sb + a_row_off
                              + (uint32_t)(mf * 16 * GSTRIDE * 2) + kofs + a_col_off;
                uint32_t ah[4];
                ldmx4(ah, addr);
#pragma unroll
                for (int nf = 0; nf < 8; nf++)
                    mma_fp16(acc[mf][nf], ah, bb[nf][0], bb[nf][1]);
            }
        }
        __syncthreads();
        if (ch + 2 < NCH) { load_stage(ch + 2, ch & 1); CP_COMMIT(); }
        if (ch + 1 < NCH) {
            if (ch + 2 < NCH) { CP_WAIT(1); } else { CP_WAIT(0); }
            __syncthreads();
        }
    }

#pragma unroll
    for (int mf = 0; mf < 2; mf++) {
        int r0 = m0 + wm * 32 + mf * 16 + (lane >> 2);
        int r1 = r0 + 8;
#pragma unroll
        for (int nf = 0; nf < 8; nf++) {
            int gcol = wn * 64 + nf * 8 + (lane & 3) * 2;
            float b0 = __ldg(bias + gcol);
            float b1 = __ldg(bias + gcol + 1);
            int half = gcol >> 7, pcol = gcol & 127;
            float* dst = Cout + (size_t)half * MTOT * 128;
            *(float2*)(dst + (size_t)r0 * 128 + pcol) =
                make_float2(acc[mf][nf][0] + b0, acc[mf][nf][1] + b1);
            *(float2*)(dst + (size_t)r1 * 128 + pcol) =
                make_float2(acc[mf][nf][2] + b0, acc[mf][nf][3] + b1);
        }
    }
}

// ---------------------------------------------------------------------------
// HMMA block-sparse flash attention, fp16 2-term (S and PV protected).
// Grid (NBQ, 2, BQ); 128 threads; 2 CTAs/SM; double-buffered K/V; LPT order.
// Epilogue: single fp16 output (feeds 1-term out GEMM).
// ---------------------------------------------------------------------------
#define AST   136
#define AMATB (64 * AST * 2)            // 17408 bytes per 64x128 matrix
#define ATT_SMEM (6 * AMATB)            // 104448

__global__ __launch_bounds__(128, 2) void attn_mma()
{
    extern __shared__ __align__(128) char sma[];
    uint32_t sb = smem_to_u32(sma);

    int tid  = threadIdx.x;
    int warp = tid >> 5, lane = tid & 31;
    int qb   = NBQ - 1 - blockIdx.x;     // LPT order
    int part = blockIdx.y;
    int b    = blockIdx.z;

    const __half* Qh = g_QKVh + (size_t)(0 + part) * MTOT * 128;
    const __half* Ql = g_QKVl + (size_t)(0 + part) * MTOT * 128;
    const __half* Kp = g_QKVh + (size_t)(2 + part) * MTOT * 128;
    const __half* Vp = g_QKVh + (size_t)(4 + part) * MTOT * 128;

    int qrow0 = b * LQ + qb * 64;
    const float SC = 0.08838834764831845f * 1.4426950408889634f;

    auto load_q = [&]() {
#pragma unroll
        for (int i = 0; i < 16; i++) {
            int e = tid + i * 128;
            int mat = e >> 10;
            int idx = e & 1023;
            int r = idx >> 4, c = idx & 15;
            const __half* src = (mat ? Ql : Qh) + (size_t)(qrow0 + r) * 128 + c * 8;
            cp16(sb + (uint32_t)(mat * AMATB) + (uint32_t)(r * AST + c * 8) * 2, src);
        }
    };
    auto load_kv = [&](int kb, int s) {
        int krow0 = b * LQ + kb * 64;
        uint32_t stb = sb + (uint32_t)((2 + 2 * s) * AMATB);
#pragma unroll
        for (int i = 0; i < 16; i++) {
            int e = tid + i * 128;
            int mat = e >> 10;
            int idx = e & 1023;
            int r = idx >> 4, c = idx & 15;
            const __half* src = (mat ? Vp : Kp) + (size_t)(krow0 + r) * 128 + c * 8;
            cp16(stb + (uint32_t)(mat * AMATB) + (uint32_t)(r * AST + c * 8) * 2, src);
        }
    };

    float O[16][4];
#pragma unroll
    for (int nf = 0; nf < 16; nf++)
#pragma unroll
        for (int j = 0; j < 4; j++) O[nf][j] = 0.f;
    float m2_0 = -1e30f, m2_1 = -1e30f;
    float l0 = 0.f, l1 = 0.f;

    int cnt = g_cnt[qb];
    const int* list = g_list[qb];

    load_q(); load_kv(list[0], 0); CP_COMMIT();
    if (cnt > 1) { load_kv(list[1], 1); CP_COMMIT(); }
    if (cnt > 1) { CP_WAIT(1); } else { CP_WAIT(0); }
    __syncthreads();

    int li = lane & 15;
    uint32_t a_off  = (uint32_t)((warp * 16 + li) * AST + (lane >> 4) * 8) * 2;
    uint32_t kv_row = (uint32_t)(li * AST + (lane >> 4) * 8) * 2;

    for (int i = 0; i < cnt; i++) {
        int s = i & 1;
        uint32_t sK = sb + (uint32_t)((2 + 2 * s) * AMATB);
        uint32_t sV = sK + AMATB;

        float sv[8][4];
#pragma unroll
        for (int nf = 0; nf < 8; nf++)
#pragma unroll
            for (int j = 0; j < 4; j++) sv[nf][j] = 0.f;

#pragma unroll
        for (int kd = 0; kd < 8; kd++) {
            uint32_t qaddr = sb + a_off + (uint32_t)(kd * 16) * 2;
            uint32_t aH[4], aL[4];
            ldmx4(aH, qaddr);
            ldmx4(aL, qaddr + AMATB);
#pragma unroll
            for (int jg = 0; jg < 4; jg++) {
                uint32_t kaddr = sK + kv_row
                               + (uint32_t)(jg * 16 * AST + kd * 16) * 2;
                uint32_t bK[4];
                ldmx4(bK, kaddr);
                mma_fp16(sv[jg * 2],     aH, bK[0], bK[2]);
                mma_fp16(sv[jg * 2],     aL, bK[0], bK[2]);
                mma_fp16(sv[jg * 2 + 1], aH, bK[1], bK[3]);
                mma_fp16(sv[jg * 2 + 1], aL, bK[1], bK[3]);
            }
        }

        float mx0 = -1e30f, mx1 = -1e30f;
#pragma unroll
        for (int nf = 0; nf < 8; nf++) {
#pragma unroll
            for (int j = 0; j < 4; j++) sv[nf][j] *= SC;
            mx0 = fmaxf(mx0, fmaxf(sv[nf][0], sv[nf][1]));
            mx1 = fmaxf(mx1, fmaxf(sv[nf][2], sv[nf][3]));
        }
        mx0 = fmaxf(mx0, __shfl_xor_sync(0xffffffffu, mx0, 1));
        mx0 = fmaxf(mx0, __shfl_xor_sync(0xffffffffu, mx0, 2));
        mx1 = fmaxf(mx1, __shfl_xor_sync(0xffffffffu, mx1, 1));
        mx1 = fmaxf(mx1, __shfl_xor_sync(0xffffffffu, mx1, 2));

        float m0n = fmaxf(m2_0, mx0);
        float m1n = fmaxf(m2_1, mx1);
        float cor0 = exp2f(m2_0 - m0n);
        float cor1 = exp2f(m2_1 - m1n);
        m2_0 = m0n; m2_1 = m1n;

        uint32_t ph[8][2], pl[8][2];
        float ls0 = 0.f, ls1 = 0.f;
#pragma unroll
        for (int nf = 0; nf < 8; nf++) {
            float p0 = exp2f(sv[nf][0] - m0n);
            float p1 = exp2f(sv[nf][1] - m0n);
            float p2 = exp2f(sv[nf][2] - m1n);
            float p3 = exp2f(sv[nf][3] - m1n);
            ls0 += p0 + p1; ls1 += p2 + p3;
            split2h(p0, p1, ph[nf][0], pl[nf][0]);
            split2h(p2, p3, ph[nf][1], pl[nf][1]);
        }
        ls0 += __shfl_xor_sync(0xffffffffu, ls0, 1);
        ls0 += __shfl_xor_sync(0xffffffffu, ls0, 2);
        ls1 += __shfl_xor_sync(0xffffffffu, ls1, 1);
        ls1 += __shfl_xor_sync(0xffffffffu, ls1, 2);
        l0 = l0 * cor0 + ls0;
        l1 = l1 * cor1 + ls1;

#pragma unroll
        for (int nf = 0; nf < 16; nf++) {
            O[nf][0] *= cor0; O[nf][1] *= cor0;
            O[nf][2] *= cor1; O[nf][3] *= cor1;
        }

#pragma unroll
        for (int kk = 0; kk < 4; kk++) {
            uint32_t aH[4] = {ph[2*kk][0], ph[2*kk][1], ph[2*kk+1][0], ph[2*kk+1][1]};
            uint32_t aL[4] = {pl[2*kk][0], pl[2*kk][1], pl[2*kk+1][0], pl[2*kk+1][1]};
#pragma unroll
            for (int dg = 0; dg < 8; dg++) {
                uint32_t vaddr = sV + kv_row
                               + (uint32_t)(kk * 16 * AST + dg * 16) * 2;
                uint32_t vV[4];
                ldmx4t(vV, vaddr);
                mma_fp16(O[dg * 2],     aH, vV[0], vV[1]);
                mma_fp16(O[dg * 2],     aL, vV[0], vV[1]);
                mma_fp16(O[dg * 2 + 1], aH, vV[2], vV[3]);
                mma_fp16(O[dg * 2 + 1], aL, vV[2], vV[3]);
            }
        }

        __syncthreads();
        if (i + 2 < cnt) { load_kv(list[i + 2], s); CP_COMMIT(); }
        if (i + 1 < cnt) {
            if (i + 2 < cnt) { CP_WAIT(1); } else { CP_WAIT(0); }
            __syncthreads();
        }
    }

    // epilogue: normalized output, single fp16
    float inv0 = 1.f / l0, inv1 = 1.f / l1;
    int r0 = qrow0 + warp * 16 + (lane >> 2);
    int r1 = r0 + 8;
#pragma unroll
    for (int nf = 0; nf < 16; nf++) {
        int col = part * 128 + nf * 8 + (lane & 3) * 2;
        *(uint32_t*)(g_Ath + (size_t)r0 * 256 + col) =
            pack_h2(O[nf][0] * inv0, O[nf][1] * inv0);
        *(uint32_t*)(g_Ath + (size_t)r1 * 256 + col) =
            pack_h2(O[nf][2] * inv1, O[nf][3] * inv1);
    }
}

// ---------------------------------------------------------------------------
// Launch
// ---------------------------------------------------------------------------
extern "C" void kernel_launch(void* const* d_in, const int* in_sizes, int n_in,
                              void* d_out, int out_size)
{
    const float* xin[6];
    for (int i = 0; i < 6; i++) xin[i] = (const float*)d_in[i];
    const float* W_qkv  = (const float*)d_in[6];
    const float* b_qkv  = (const float*)d_in[7];
    const float* W_out  = (const float*)d_in[8];
    const float* b_out  = (const float*)d_in[9];
    const void*  mask   = d_in[10];
    float* out = (float*)d_out;
    (void)in_sizes; (void)n_in; (void)out_size;

    cudaFuncSetAttribute(attn_mma, cudaFuncAttributeMaxDynamicSharedMemorySize,
                         ATT_SMEM);
    cudaFuncSetAttribute(gemm_qkv, cudaFuncAttributeMaxDynamicSharedMemorySize,
                         GEMM_SMEM);
    cudaFuncSetAttribute(gemm_out, cudaFuncAttributeMaxDynamicSharedMemorySize,
                         GEMM_SMEM);

    __half *Wq, *Ath, *Wo;
    cudaGetSymbolAddress((void**)&Wq,  g_Wq);
    cudaGetSymbolAddress((void**)&Ath, g_Ath);
    cudaGetSymbolAddress((void**)&Wo,  g_Wo);

    prep_kernel<<<WQ_BLKS + WO_BLKS + 1, 256>>>(                          // 0
        (const float4*)W_qkv, (const float4*)W_out, mask);
    gemm_qkv<<<dim3(3, MTOT / 128), 512, GEMM_SMEM>>>(                    // 1
        xin[0], xin[1], xin[2], xin[3], xin[4], xin[5], Wq, b_qkv);
    attn_mma<<<dim3(NBQ, 2, BQ), 128, ATT_SMEM>>>();                      // 2
    gemm_out<<<dim3(1, MTOT / 128), 512, GEMM_SMEM>>>(                    // 3
        Ath, Wo, b_out, out);
}

// round 15
// speedup vs baseline: 2.2113x; 1.3446x over previous
#include <cuda_runtime.h>
#include <cuda_fp16.h>
#include <math_constants.h>
#include <cstdint>

// Problem constants
#define BQ   4
#define LQ   4096
#define DQ   128
#define NBQ  64
#define MTOT (BQ * LQ)     // 16384 rows

// ---------------------------------------------------------------------------
// Scratch (__device__ globals; no allocations allowed). All fp16 single.
// ---------------------------------------------------------------------------
__device__ __half g_Wq[768 * 768];           // W_qkv fp16
__device__ __half g_QKV[6 * MTOT * DQ];      // Q,K,V planes, single fp16
__device__ __half g_At[MTOT * 256];          // attention out, single fp16
__device__ __half g_Wo[256 * 256];           // W_out fp16
__device__ int g_cnt[NBQ];
__device__ int g_list[NBQ][NBQ];

// ---------------------------------------------------------------------------
// Helpers
// ---------------------------------------------------------------------------
__device__ __forceinline__ uint32_t smem_to_u32(const void* p) {
    uint32_t a;
    asm("{ .reg .u64 t; cvta.to.shared.u64 t, %1; cvt.u32.u64 %0, t; }" : "=r"(a) : "l"(p));
    return a;
}
__device__ __forceinline__ void cp16(uint32_t dst_smem, const void* src) {
    asm volatile("cp.async.cg.shared.global [%0], [%1], 16;" :: "r"(dst_smem), "l"(src));
}
#define CP_COMMIT() asm volatile("cp.async.commit_group;" ::: "memory")
#define CP_WAIT(n)  asm volatile("cp.async.wait_group %0;" :: "n"(n) : "memory")

__device__ __forceinline__ void ldmx4(uint32_t* r, uint32_t addr) {
    asm volatile("ldmatrix.sync.aligned.m8n8.x4.shared.b16 {%0,%1,%2,%3}, [%4];"
                 : "=r"(r[0]), "=r"(r[1]), "=r"(r[2]), "=r"(r[3]) : "r"(addr));
}
__device__ __forceinline__ void ldmx4t(uint32_t* r, uint32_t addr) {
    asm volatile("ldmatrix.sync.aligned.m8n8.x4.trans.shared.b16 {%0,%1,%2,%3}, [%4];"
                 : "=r"(r[0]), "=r"(r[1]), "=r"(r[2]), "=r"(r[3]) : "r"(addr));
}
__device__ __forceinline__ void ldmx2(uint32_t* r, uint32_t addr) {
    asm volatile("ldmatrix.sync.aligned.m8n8.x2.shared.b16 {%0,%1}, [%2];"
                 : "=r"(r[0]), "=r"(r[1]) : "r"(addr));
}
__device__ __forceinline__ void mma_fp16(float* c, const uint32_t* a,
                                         uint32_t b0, uint32_t b1) {
    asm volatile(
        "mma.sync.aligned.m16n8k16.row.col.f32.f16.f16.f32 "
        "{%0,%1,%2,%3}, {%4,%5,%6,%7}, {%8,%9}, {%0,%1,%2,%3};"
        : "+f"(c[0]), "+f"(c[1]), "+f"(c[2]), "+f"(c[3])
        : "r"(a[0]), "r"(a[1]), "r"(a[2]), "r"(a[3]), "r"(b0), "r"(b1));
}
__device__ __forceinline__ uint32_t pack_h2(float a, float b) {
    __half2 t = __floats2half2_rn(a, b);
    return *(uint32_t*)&t;
}

// ---------------------------------------------------------------------------
// Fused prep: block-mask compaction + W_qkv cvt + W_out cvt, one launch.
// ---------------------------------------------------------------------------
#define WQ_BLKS 576     // 768*768/4 / 256
#define WO_BLKS 64      // 256*256/4 / 256
__global__ void prep_kernel(const float4* __restrict__ Wq_src,
                            const float4* __restrict__ Wo_src,
                            const void* __restrict__ mask)
{
    int bx = blockIdx.x;
    if (bx < WQ_BLKS) {
        int i = bx * 256 + threadIdx.x;
        float4 v = Wq_src[i];
        ((uint2*)g_Wq)[i] = make_uint2(pack_h2(v.x, v.y), pack_h2(v.z, v.w));
    } else if (bx < WQ_BLKS + WO_BLKS) {
        int i = (bx - WQ_BLKS) * 256 + threadIdx.x;
        float4 v = Wo_src[i];
        ((uint2*)g_Wo)[i] = make_uint2(pack_h2(v.x, v.y), pack_h2(v.z, v.w));
    } else {
        int qb = threadIdx.x;
        if (qb >= NBQ) return;
        const float* mf = (const float*)mask;
        const int*   mi = (const int*)mask;
        const unsigned char* mb = (const unsigned char*)mask;
        int mode;
        if (mf[0] == 1.0f)   mode = 0;
        else if (mi[0] == 1) mode = 1;
        else                 mode = 2;
        int cnt = 0;
        for (int kb = 0; kb <= qb; kb++) {
            size_t idx = (size_t)(qb * 64) * (size_t)LQ + (size_t)(kb * 64);
            bool on;
            if (mode == 0)      on = (mf[idx] != 0.0f);
            else if (mode == 1) on = (mi[idx] != 0);
            else                on = (mb[idx] != 0);
            if (on) g_list[qb][cnt++] = kb;
        }
        g_cnt[qb] = cnt;
    }
}

// ---------------------------------------------------------------------------
// GEMM geometry: CTA tile 128(M) x 256(N) x 32(K), 512 threads = 16 warps
// (4M x 4N); warp tile 32x64. smem rows stride 40 fp16. 1-term fp16.
// ---------------------------------------------------------------------------
#define GSTRIDE 40
#define A_MATB  (128 * GSTRIDE * 2)     // 10240 B
#define B_MATB  (256 * GSTRIDE * 2)     // 20480 B
#define STAGEB  (A_MATB + B_MATB)       // A, B = 30720
#define GEMM_SMEM (2 * STAGEB)          // 61440

// ---------------------------------------------------------------------------
// QKV GEMM (1-term): Y[16384,768] = X @ Wq^T + b. Grid (3, 128).
// A = X fp32 converted to single fp16 in the loader. Output single fp16.
// ---------------------------------------------------------------------------
__global__ __launch_bounds__(512, 1) void gemm_qkv(
    const float* __restrict__ x0, const float* __restrict__ x1,
    const float* __restrict__ x2, const float* __restrict__ x3,
    const float* __restrict__ x4, const float* __restrict__ x5,
    const __half* __restrict__ W, const float* __restrict__ bias)
{
    constexpr int NCH = 24;   // 768 / 32

    extern __shared__ __align__(128) char smc[];
    uint32_t sbase0 = smem_to_u32(smc);

    int tid  = threadIdx.x;
    int warp = tid >> 5, lane = tid & 31;
    int wm = warp & 3;
    int wn = warp >> 2;
    int m0 = blockIdx.y * 128;
    int n0 = blockIdx.x * 256;

    float4 pre[2];

    auto ldA = [&](int ch) {
        int k0 = ch * 32;
        int pl = k0 >> 7, kc = k0 & 127;
        const float* xp = (pl == 0) ? x0 : (pl == 1) ? x1 : (pl == 2) ? x2
                        : (pl == 3) ? x3 : (pl == 4) ? x4 : x5;
        int r = tid >> 2, seg = tid & 3;
        const float* s = xp + (size_t)(m0 + r) * 128 + kc + seg * 8;
        pre[0] = *(const float4*)s;
        pre[1] = *(const float4*)(s + 4);
    };
    auto stsA = [&](int buf) {
        char* base = smc + buf * STAGEB;
        int r = tid >> 2, seg = tid & 3;
        float4 v0 = pre[0], v1 = pre[1];
        uint32_t h0 = pack_h2(v0.x, v0.y), h1 = pack_h2(v0.z, v0.w);
        uint32_t h2 = pack_h2(v1.x, v1.y), h3 = pack_h2(v1.z, v1.w);
        uint32_t off = (uint32_t)(r * GSTRIDE + seg * 8) * 2;
        *(uint4*)(base + off) = make_uint4(h0, h1, h2, h3);
    };
    auto ldB = [&](int ch, int buf) {
        int k0 = ch * 32;
        uint32_t sbB = sbase0 + buf * STAGEB + A_MATB;
#pragma unroll
        for (int i = 0; i < 2; i++) {
            int e = tid + i * 512;
            int r = e >> 2, seg = e & 3;
            size_t gb = (size_t)(n0 + r) * 768 + k0 + seg * 8;
            cp16(sbB + (uint32_t)(r * GSTRIDE + seg * 8) * 2, W + gb);
        }
    };

    float acc[2][8][4];
#pragma unroll
    for (int mf = 0; mf < 2; mf++)
#pragma unroll
        for (int nf = 0; nf < 8; nf++)
#pragma unroll
            for (int j = 0; j < 4; j++) acc[mf][nf][j] = 0.f;

    ldA(0); stsA(0); ldB(0, 0); CP_COMMIT();
    ldA(1); stsA(1); ldB(1, 1); CP_COMMIT();
    CP_WAIT(1);
    __syncthreads();

    int li = lane & 15;
    uint32_t a_row_off = (uint32_t)((wm * 32 + li) * GSTRIDE) * 2;
    uint32_t a_col_off = (uint32_t)((lane >> 4) * 8) * 2;
    uint32_t b_row_off = (uint32_t)A_MATB + (uint32_t)((wn * 64 + (li & 7)) * GSTRIDE) * 2;
    uint32_t b_col_off = (uint32_t)((li >> 3) * 8) * 2;

    for (int ch = 0; ch < NCH; ch++) {
        uint32_t sb = sbase0 + (ch & 1) * STAGEB;
        if (ch + 2 < NCH) ldA(ch + 2);
#pragma unroll
        for (int k16 = 0; k16 < 2; k16++) {
            uint32_t kofs = (uint32_t)(k16 * 16) * 2;
            uint32_t bb[8][2];
#pragma unroll
            for (int nf = 0; nf < 8; nf++) {
                uint32_t addr = sb + b_row_off
                              + (uint32_t)(nf * 8 * GSTRIDE * 2) + kofs + b_col_off;
                ldmx2(bb[nf], addr);
            }
#pragma unroll
            for (int mf = 0; mf < 2; mf++) {
                uint32_t addr = sb + a_row_off
                              + (uint32_t)(mf * 16 * GSTRIDE * 2) + kofs + a_col_off;
                uint32_t ah[4];
                ldmx4(ah, addr);
#pragma unroll
                for (int nf = 0; nf < 8; nf++)
                    mma_fp16(acc[mf][nf], ah, bb[nf][0], bb[nf][1]);
            }
        }
        __syncthreads();
        if (ch + 2 < NCH) { stsA(ch & 1); ldB(ch + 2, ch & 1); CP_COMMIT(); }
        if (ch + 1 < NCH) {
            if (ch + 2 < NCH) { CP_WAIT(1); } else { CP_WAIT(0); }
            __syncthreads();
        }
    }

#pragma unroll
    for (int mf = 0; mf < 2; mf++) {
        int r0 = m0 + wm * 32 + mf * 16 + (lane >> 2);
        int r1 = r0 + 8;
#pragma unroll
        for (int nf = 0; nf < 8; nf++) {
            int gcol = n0 + wn * 64 + nf * 8 + (lane & 3) * 2;
            float b0 = __ldg(bias + gcol);
            float b1 = __ldg(bias + gcol + 1);
            int plane = gcol >> 7, pcol = gcol & 127;
            size_t base = (size_t)plane * MTOT * 128;
            *(uint32_t*)(g_QKV + base + (size_t)r0 * 128 + pcol) =
                pack_h2(acc[mf][nf][0] + b0, acc[mf][nf][1] + b1);
            *(uint32_t*)(g_QKV + base + (size_t)r1 * 128 + pcol) =
                pack_h2(acc[mf][nf][2] + b0, acc[mf][nf][3] + b1);
        }
    }
}

// ---------------------------------------------------------------------------
// Output GEMM (1-term): out[16384,256] = At @ Wo^T + b. Grid (1, 128).
// ---------------------------------------------------------------------------
__global__ __launch_bounds__(512, 1) void gemm_out(
    const __half* __restrict__ Ah, const __half* __restrict__ B,
    const float* __restrict__ bias, float* __restrict__ Cout)
{
    constexpr int NCH = 8;    // 256 / 32

    extern __shared__ __align__(128) char smc[];
    uint32_t sbase0 = smem_to_u32(smc);

    int tid  = threadIdx.x;
    int warp = tid >> 5, lane = tid & 31;
    int wm = warp & 3;
    int wn = warp >> 2;
    int m0 = blockIdx.y * 128;

    auto load_stage = [&](int ch, int buf) {
        int k0 = ch * 32;
        uint32_t sb = sbase0 + buf * STAGEB;
        {
            int r = tid >> 2, seg = tid & 3;
            uint32_t off = (uint32_t)(r * GSTRIDE + seg * 8) * 2;
            size_t ga = (size_t)(m0 + r) * 256 + k0 + seg * 8;
            cp16(sb + off, Ah + ga);
        }
#pragma unroll
        for (int i = 0; i < 2; i++) {
            int e = tid + i * 512;
            int r = e >> 2, seg = e & 3;
            size_t gb = (size_t)r * 256 + k0 + seg * 8;
            cp16(sb + A_MATB + (uint32_t)(r * GSTRIDE + seg * 8) * 2, B + gb);
        }
    };

    float acc[2][8][4];
#pragma unroll
    for (int mf = 0; mf < 2; mf++)
#pragma unroll
        for (int nf = 0; nf < 8; nf++)
#pragma unroll
            for (int j = 0; j < 4; j++) acc[mf][nf][j] = 0.f;

    load_stage(0, 0); CP_COMMIT();
    load_stage(1, 1); CP_COMMIT();
    CP_WAIT(1);
    __syncthreads();

    int li = lane & 15;
    uint32_t a_row_off = (uint32_t)((wm * 32 + li) * GSTRIDE) * 2;
    uint32_t a_col_off = (uint32_t)((lane >> 4) * 8) * 2;
    uint32_t b_row_off = (uint32_t)A_MATB + (uint32_t)((wn * 64 + (li & 7)) * GSTRIDE) * 2;
    uint32_t b_col_off = (uint32_t)((li >> 3) * 8) * 2;

    for (int ch = 0; ch < NCH; ch++) {
        uint32_t sb = sbase0 + (ch & 1) * STAGEB;
#pragma unroll
        for (int k16 = 0; k16 < 2; k16++) {
            uint32_t kofs = (uint32_t)(k16 * 16) * 2;
            uint32_t bb[8][2];
#pragma unroll
            for (int nf = 0; nf < 8; nf++) {
                uint32_t addr = sb + b_row_off
                              + (uint32_t)(nf * 8 * GSTRIDE * 2) + kofs + b_col_off;
                ldmx2(bb[nf], addr);
            }
#pragma unroll
            for (int mf = 0; mf < 2; mf++) {
                uint32_t addr = sb + a_row_off
                              + (uint32_t)(mf * 16 * GSTRIDE * 2) + kofs + a_col_off;
                uint32_t ah[4];
                ldmx4(ah, addr);
#pragma unroll
                for (int nf = 0; nf < 8; nf++)
                    mma_fp16(acc[mf][nf], ah, bb[nf][0], bb[nf][1]);
            }
        }
        __syncthreads();
        if (ch + 2 < NCH) { load_stage(ch + 2, ch & 1); CP_COMMIT(); }
        if (ch + 1 < NCH) {
            if (ch + 2 < NCH) { CP_WAIT(1); } else { CP_WAIT(0); }
            __syncthreads();
        }
    }

#pragma unroll
    for (int mf = 0; mf < 2; mf++) {
        int r0 = m0 + wm * 32 + mf * 16 + (lane >> 2);
        int r1 = r0 + 8;
#pragma unroll
        for (int nf = 0; nf < 8; nf++) {
            int gcol = wn * 64 + nf * 8 + (lane & 3) * 2;
            float b0 = __ldg(bias + gcol);
            float b1 = __ldg(bias + gcol + 1);
            int half = gcol >> 7, pcol = gcol & 127;
            float* dst = Cout + (size_t)half * MTOT * 128;
            *(float2*)(dst + (size_t)r0 * 128 + pcol) =
                make_float2(acc[mf][nf][0] + b0, acc[mf][nf][1] + b1);
            *(float2*)(dst + (size_t)r1 * 128 + pcol) =
                make_float2(acc[mf][nf][2] + b0, acc[mf][nf][3] + b1);
        }
    }
}

// ---------------------------------------------------------------------------
// HMMA block-sparse flash attention, fp16 1-term (Q,K,V,P all single fp16).
// Grid (NBQ, 2, BQ); 128 threads; 2 CTAs/SM; double-buffered K/V; LPT order.
// smem: Q + 2 stages x (K,V) = 5 matrices = 87040 B.
// ---------------------------------------------------------------------------
#define AST   136
#define AMATB (64 * AST * 2)            // 17408 B per 64x128 matrix
#define ATT_SMEM (5 * AMATB)            // 87040

__global__ __launch_bounds__(128, 2) void attn_mma()
{
    extern __shared__ __align__(128) char sma[];
    uint32_t sb = smem_to_u32(sma);

    int tid  = threadIdx.x;
    int warp = tid >> 5, lane = tid & 31;
    int qb   = NBQ - 1 - blockIdx.x;     // LPT order
    int part = blockIdx.y;
    int b    = blockIdx.z;

    const __half* Qp = g_QKV + (size_t)(0 + part) * MTOT * 128;
    const __half* Kp = g_QKV + (size_t)(2 + part) * MTOT * 128;
    const __half* Vp = g_QKV + (size_t)(4 + part) * MTOT * 128;

    int qrow0 = b * LQ + qb * 64;
    const float SC = 0.08838834764831845f * 1.4426950408889634f;

    auto load_q = [&]() {
#pragma unroll
        for (int i = 0; i < 8; i++) {
            int e = tid + i * 128;            // 0..1023 chunks
            int r = e >> 4, c = e & 15;
            cp16(sb + (uint32_t)(r * AST + c * 8) * 2,
                 Qp + (size_t)(qrow0 + r) * 128 + c * 8);
        }
    };
    auto load_kv = [&](int kb, int s) {
        int krow0 = b * LQ + kb * 64;
        uint32_t stb = sb + (uint32_t)((1 + 2 * s) * AMATB);
#pragma unroll
        for (int i = 0; i < 16; i++) {
            int e = tid + i * 128;            // 0..2047: K then V
            int mat = e >> 10;
            int idx = e & 1023;
            int r = idx >> 4, c = idx & 15;
            const __half* src = (mat ? Vp : Kp) + (size_t)(krow0 + r) * 128 + c * 8;
            cp16(stb + (uint32_t)(mat * AMATB) + (uint32_t)(r * AST + c * 8) * 2, src);
        }
    };

    float O[16][4];
#pragma unroll
    for (int nf = 0; nf < 16; nf++)
#pragma unroll
        for (int j = 0; j < 4; j++) O[nf][j] = 0.f;
    float m2_0 = -1e30f, m2_1 = -1e30f;
    float l0 = 0.f, l1 = 0.f;

    int cnt = g_cnt[qb];
    const int* list = g_list[qb];

    load_q(); load_kv(list[0], 0); CP_COMMIT();
    if (cnt > 1) { load_kv(list[1], 1); CP_COMMIT(); }
    if (cnt > 1) { CP_WAIT(1); } else { CP_WAIT(0); }
    __syncthreads();

    int li = lane & 15;
    uint32_t a_off  = (uint32_t)((warp * 16 + li) * AST + (lane >> 4) * 8) * 2;
    uint32_t kv_row = (uint32_t)(li * AST + (lane >> 4) * 8) * 2;

    for (int i = 0; i < cnt; i++) {
        int s = i & 1;
        uint32_t sK = sb + (uint32_t)((1 + 2 * s) * AMATB);
        uint32_t sV = sK + AMATB;

        // ---- S = Q @ K^T (1-term) ----
        float sv[8][4];
#pragma unroll
        for (int nf = 0; nf < 8; nf++)
#pragma unroll
            for (int j = 0; j < 4; j++) sv[nf][j] = 0.f;

#pragma unroll
        for (int kd = 0; kd < 8; kd++) {
            uint32_t qaddr = sb + a_off + (uint32_t)(kd * 16) * 2;
            uint32_t aH[4];
            ldmx4(aH, qaddr);
#pragma unroll
            for (int jg = 0; jg < 4; jg++) {
                uint32_t kaddr = sK + kv_row
                               + (uint32_t)(jg * 16 * AST + kd * 16) * 2;
                uint32_t bK[4];
                ldmx4(bK, kaddr);
                mma_fp16(sv[jg * 2],     aH, bK[0], bK[2]);
                mma_fp16(sv[jg * 2 + 1], aH, bK[1], bK[3]);
            }
        }

        // ---- online softmax (log2 domain) ----
        float mx0 = -1e30f, mx1 = -1e30f;
#pragma unroll
        for (int nf = 0; nf < 8; nf++) {
#pragma unroll
            for (int j = 0; j < 4; j++) sv[nf][j] *= SC;
            mx0 = fmaxf(mx0, fmaxf(sv[nf][0], sv[nf][1]));
            mx1 = fmaxf(mx1, fmaxf(sv[nf][2], sv[nf][3]));
        }
        mx0 = fmaxf(mx0, __shfl_xor_sync(0xffffffffu, mx0, 1));
        mx0 = fmaxf(mx0, __shfl_xor_sync(0xffffffffu, mx0, 2));
        mx1 = fmaxf(mx1, __shfl_xor_sync(0xffffffffu, mx1, 1));
        mx1 = fmaxf(mx1, __shfl_xor_sync(0xffffffffu, mx1, 2));

        float m0n = fmaxf(m2_0, mx0);
        float m1n = fmaxf(m2_1, mx1);
        float cor0 = exp2f(m2_0 - m0n);
        float cor1 = exp2f(m2_1 - m1n);
        m2_0 = m0n; m2_1 = m1n;

        uint32_t ph[8][2];
        float ls0 = 0.f, ls1 = 0.f;
#pragma unroll
        for (int nf = 0; nf < 8; nf++) {
            float p0 = exp2f(sv[nf][0] - m0n);
            float p1 = exp2f(sv[nf][1] - m0n);
            float p2 = exp2f(sv[nf][2] - m1n);
            float p3 = exp2f(sv[nf][3] - m1n);
            ls0 += p0 + p1; ls1 += p2 + p3;
            ph[nf][0] = pack_h2(p0, p1);
            ph[nf][1] = pack_h2(p2, p3);
        }
        ls0 += __shfl_xor_sync(0xffffffffu, ls0, 1);
        ls0 += __shfl_xor_sync(0xffffffffu, ls0, 2);
        ls1 += __shfl_xor_sync(0xffffffffu, ls1, 1);
        ls1 += __shfl_xor_sync(0xffffffffu, ls1, 2);
        l0 = l0 * cor0 + ls0;
        l1 = l1 * cor1 + ls1;

        // ---- rescale O ----
#pragma unroll
        for (int nf = 0; nf < 16; nf++) {
            O[nf][0] *= cor0; O[nf][1] *= cor0;
            O[nf][2] *= cor1; O[nf][3] *= cor1;
        }

        // ---- O += P @ V (1-term) ----
#pragma unroll
        for (int kk = 0; kk < 4; kk++) {
            uint32_t aH[4] = {ph[2*kk][0], ph[2*kk][1], ph[2*kk+1][0], ph[2*kk+1][1]};
#pragma unroll
            for (int dg = 0; dg < 8; dg++) {
                uint32_t vaddr = sV + kv_row
                               + (uint32_t)(kk * 16 * AST + dg * 16) * 2;
                uint32_t vV[4];
                ldmx4t(vV, vaddr);
                mma_fp16(O[dg * 2],     aH, vV[0], vV[1]);
                mma_fp16(O[dg * 2 + 1], aH, vV[2], vV[3]);
            }
        }

        __syncthreads();
        if (i + 2 < cnt) { load_kv(list[i + 2], s); CP_COMMIT(); }
        if (i + 1 < cnt) {
            if (i + 2 < cnt) { CP_WAIT(1); } else { CP_WAIT(0); }
            __syncthreads();
        }
    }

    // epilogue: normalized output, single fp16
    float inv0 = 1.f / l0, inv1 = 1.f / l1;
    int r0 = qrow0 + warp * 16 + (lane >> 2);
    int r1 = r0 + 8;
#pragma unroll
    for (int nf = 0; nf < 16; nf++) {
        int col = part * 128 + nf * 8 + (lane & 3) * 2;
        *(uint32_t*)(g_At + (size_t)r0 * 256 + col) =
            pack_h2(O[nf][0] * inv0, O[nf][1] * inv0);
        *(uint32_t*)(g_At + (size_t)r1 * 256 + col) =
            pack_h2(O[nf][2] * inv1, O[nf][3] * inv1);
    }
}

// ---------------------------------------------------------------------------
// Launch
// ---------------------------------------------------------------------------
extern "C" void kernel_launch(void* const* d_in, const int* in_sizes, int n_in,
                              void* d_out, int out_size)
{
    const float* xin[6];
    for (int i = 0; i < 6; i++) xin[i] = (const float*)d_in[i];
    const float* W_qkv  = (const float*)d_in[6];
    const float* b_qkv  = (const float*)d_in[7];
    const float* W_out  = (const float*)d_in[8];
    const float* b_out  = (const float*)d_in[9];
    const void*  mask   = d_in[10];
    float* out = (float*)d_out;
    (void)in_sizes; (void)n_in; (void)out_size;

    cudaFuncSetAttribute(attn_mma, cudaFuncAttributeMaxDynamicSharedMemorySize,
                         ATT_SMEM);
    cudaFuncSetAttribute(gemm_qkv, cudaFuncAttributeMaxDynamicSharedMemorySize,
                         GEMM_SMEM);
    cudaFuncSetAttribute(gemm_out, cudaFuncAttributeMaxDynamicSharedMemorySize,
                         GEMM_SMEM);

    __half *Wq, *At, *Wo;
    cudaGetSymbolAddress((void**)&Wq, g_Wq);
    cudaGetSymbolAddress((void**)&At, g_At);
    cudaGetSymbolAddress((void**)&Wo, g_Wo);

    prep_kernel<<<WQ_BLKS + WO_BLKS + 1, 256>>>(                          // 0
        (const float4*)W_qkv, (const float4*)W_out, mask);
    gemm_qkv<<<dim3(3, MTOT / 128), 512, GEMM_SMEM>>>(                    // 1
        xin[0], xin[1], xin[2], xin[3], xin[4], xin[5], Wq, b_qkv);
    attn_mma<<<dim3(NBQ, 2, BQ), 128, ATT_SMEM>>>();                      // 2
    gemm_out<<<dim3(1, MTOT / 128), 512, GEMM_SMEM>>>(                    // 3
        At, Wo, b_out, out);
}